// round 10
// baseline (speedup 1.0000x reference)
#include <cuda_runtime.h>
#include <math.h>
#include <stdint.h>

#define FD   128
#define EMAX 200000
#define NMAX 8000
#define AMAX 400000
#define GMAX 128
#define PI_F 3.14159265358979323846f

// ------------------------- scratch (device globals; no allocs) -------------
__device__ float g_e   [(size_t)EMAX * FD];   // edge features e
__device__ float g_agg [(size_t)EMAX * FD];   // per-block angle aggregation
__device__ float g_ef0 [(size_t)EMAX * 5];    // rbf features (incl sqrt(2/5))
__device__ float g_v   [(size_t)NMAX * FD];   // atom features
__device__ float g_gate[(size_t)NMAX * FD];   // sigmoid(v@Wg+bg) per atom
__device__ float g_pi  [(size_t)NMAX * FD];   // v @ We1[0:128]
__device__ float g_pj  [(size_t)NMAX * FD];   // v @ We1[128:256]
__device__ float g_pai [(size_t)NMAX * FD];   // v @ Wa1[0:128]
__device__ float g_paj [(size_t)NMAX * FD];   // v @ Wa1[128:256]
__device__ float g_angf[(size_t)AMAX * 16];   // rad x P x fc^2
__device__ int   g_iij [AMAX];
__device__ int   g_kat [AMAX];
__device__ int   g_boff[GMAX];
__device__ int   g_acum[GMAX + 1];

// ------------------------- helpers ----------------------------------------
__device__ __forceinline__ void fma4(float4& a, float s, float4 b){
    a.x = fmaf(s, b.x, a.x);
    a.y = fmaf(s, b.y, a.y);
    a.z = fmaf(s, b.z, a.z);
    a.w = fmaf(s, b.w, a.w);
}

// packed f32x2 helpers (FFMA2 — only reachable via PTX on sm_103a)
__device__ __forceinline__ uint64_t splat2(float s){
    uint64_t r; asm("mov.b64 %0, {%1, %1};" : "=l"(r) : "f"(s)); return r;
}
__device__ __forceinline__ uint64_t pack2(float x, float y){
    uint64_t r; asm("mov.b64 %0, {%1, %2};" : "=l"(r) : "f"(x), "f"(y)); return r;
}
__device__ __forceinline__ float2 unpack2(uint64_t v){
    float2 f; asm("mov.b64 {%0, %1}, %2;" : "=f"(f.x), "=f"(f.y) : "l"(v)); return f;
}
__device__ __forceinline__ void ffma2(uint64_t& a, uint64_t b, uint64_t c){
    asm("fma.rn.f32x2 %0, %1, %2, %0;" : "+l"(a) : "l"(b), "l"(c));
}

__device__ __forceinline__ float sigmf(float x){ return __fdividef(1.0f, 1.0f + __expf(-x)); }
__device__ __forceinline__ float swishf(float x){ return x * sigmf(x); }
__device__ __forceinline__ float4 swish4(float4 a){
    return make_float4(swishf(a.x), swishf(a.y), swishf(a.z), swishf(a.w));
}
__device__ __forceinline__ float4 sigm4(float4 a){
    return make_float4(sigmf(a.x), sigmf(a.y), sigmf(a.z), sigmf(a.w));
}
__device__ __forceinline__ float4 add4(float4 a, float4 b){
    return make_float4(a.x+b.x, a.y+b.y, a.z+b.z, a.w+b.w);
}
__device__ __forceinline__ float4 mul4(float4 a, float4 b){
    return make_float4(a.x*b.x, a.y*b.y, a.z*b.z, a.w*b.w);
}
__device__ __forceinline__ void red4(float* p, float4 v){
    asm volatile("red.global.add.v4.f32 [%0], {%1,%2,%3,%4};"
                 :: "l"(p), "f"(v.x), "f"(v.y), "f"(v.z), "f"(v.w) : "memory");
}

// ------------------------- prep kernels ------------------------------------
__global__ void k_offsets(const int* __restrict__ tnb, const int* __restrict__ tna, int G){
    if (threadIdx.x == 0 && blockIdx.x == 0){
        int ob = 0, oa = 0;
        g_acum[0] = 0;
        for (int g = 0; g < G; g++){
            g_boff[g] = ob;
            ob += tnb[g];
            oa += tna[g];
            g_acum[g + 1] = oa;
        }
    }
}

__global__ void k_angle_pre(const int* __restrict__ tbi,
                            const float* __restrict__ norm_ik,
                            const float* __restrict__ cosang,
                            const int* __restrict__ edge_index,
                            int A, int E, int G)
{
    int a = blockIdx.x * blockDim.x + threadIdx.x;
    if (a >= A) return;
    // find graph: largest g with g_acum[g] <= a
    int lo = 0, hi = G - 1;
    while (lo < hi){ int mid = (lo + hi + 1) >> 1; if (g_acum[mid] <= a) lo = mid; else hi = mid - 1; }
    int off = g_boff[lo];
    int iij = tbi[2*a]     + off;
    int iik = tbi[2*a + 1] + off;
    g_iij[a] = iij;
    g_kat[a] = edge_index[E + iik];         // recv[idx_ik]

    float r = norm_ik[a];
    float c = cosang[a];
    float x = r * 0.25f;                    // r / CUT3
    float x2 = x*x, x3 = x2*x;
    float fc = 1.0f - 6.0f*x3*x2 + 15.0f*x2*x2 - 10.0f*x3;
    float invr = 1.0f / r;
    float s2 = fc * fc * invr;              // fold 1/r + fc^2 (one fc from shrb, one from msg)
    float rad[4];
    #pragma unroll
    for (int n = 0; n < 4; n++) rad[n] = sinf((float)(n+1) * PI_F * x) * s2;
    float P0 = 1.0f, P1 = c;
    float P2 = 0.5f * (3.0f*c*c - 1.0f);
    float P3 = 0.5f * c * (5.0f*c*c - 3.0f);
    #pragma unroll
    for (int n = 0; n < 4; n++)
        *(float4*)&g_angf[(size_t)a*16 + n*4] = make_float4(rad[n]*P0, rad[n]*P1, rad[n]*P2, rad[n]*P3);
}

__global__ void k_edge_init(const float* __restrict__ edge_dist,
                            const float* __restrict__ W_enc,
                            const float* __restrict__ b_enc, int E)
{
    int gw   = (blockIdx.x * blockDim.x + threadIdx.x) >> 5;
    int lane = threadIdx.x & 31;
    if (gw >= E) return;
    float r    = edge_dist[gw];
    float invr = 1.0f / r;
    const float C = sqrtf(2.0f / 5.0f);
    float ef[5];
    #pragma unroll
    for (int n = 0; n < 5; n++) ef[n] = C * sinf((float)(n+1) * PI_F * r * 0.2f) * invr;
    if (lane < 5) g_ef0[(size_t)gw*5 + lane] = ef[lane];
    int fo = lane * 4;
    float4 acc = *(const float4*)&b_enc[fo];
    #pragma unroll
    for (int n = 0; n < 5; n++){
        float4 w = *(const float4*)&W_enc[n*FD + fo];
        fma4(acc, ef[n], w);
    }
    *(float4*)&g_e[(size_t)gw*FD + fo] = swish4(acc);
}

__global__ void k_vinit(const int* __restrict__ z, const float* __restrict__ emb, int N){
    int t = blockIdx.x * blockDim.x + threadIdx.x;
    if (t >= N * 32) return;
    int n = t >> 5, fo = (t & 31) * 4;
    *(float4*)&g_v[(size_t)n*FD + fo] = *(const float4*)&emb[(size_t)z[n]*FD + fo];
}

// ------------------- per-block: atom precompute (gate + concat parts) -------
__global__ __launch_bounds__(256)
void k_gate_pre(const float* __restrict__ Wg,  const float* __restrict__ bg,
                const float* __restrict__ We1b, const float* __restrict__ Wa1b, int N)
{
    __shared__ float sv[8][FD];
    const int warp = threadIdx.x >> 5, lane = threadIdx.x & 31;
    const int fo = lane * 4;
    for (int base = blockIdx.x * 8; base < N; base += gridDim.x * 8){
        int na = N - base; if (na > 8) na = 8;
        __syncthreads();
        for (int idx = threadIdx.x; idx < na * 32; idx += blockDim.x){
            int rr = idx >> 5, cc = (idx & 31) * 4;
            *(float4*)&sv[rr][cc] = *(const float4*)&g_v[(size_t)(base+rr)*FD + cc];
        }
        __syncthreads();
        if (warp < 5){
            const float* W = (warp == 0) ? Wg
                           : (warp == 1) ? We1b
                           : (warp == 2) ? (We1b + FD*FD)
                           : (warp == 3) ? Wa1b
                           :               (Wa1b + FD*FD);
            uint64_t acc[8][2];
            #pragma unroll
            for (int j = 0; j < 8; j++){ acc[j][0] = 0ull; acc[j][1] = 0ull; }
            #pragma unroll 4
            for (int k4 = 0; k4 < 32; k4++){
                ulonglong2 w0 = *(const ulonglong2*)&W[(k4*4+0)*FD + fo];
                ulonglong2 w1 = *(const ulonglong2*)&W[(k4*4+1)*FD + fo];
                ulonglong2 w2 = *(const ulonglong2*)&W[(k4*4+2)*FD + fo];
                ulonglong2 w3 = *(const ulonglong2*)&W[(k4*4+3)*FD + fo];
                #pragma unroll
                for (int j = 0; j < 8; j++){
                    float4 s = *(const float4*)&sv[j][k4*4];
                    uint64_t s0 = splat2(s.x), s1 = splat2(s.y);
                    uint64_t s2 = splat2(s.z), s3 = splat2(s.w);
                    ffma2(acc[j][0], s0, w0.x); ffma2(acc[j][1], s0, w0.y);
                    ffma2(acc[j][0], s1, w1.x); ffma2(acc[j][1], s1, w1.y);
                    ffma2(acc[j][0], s2, w2.x); ffma2(acc[j][1], s2, w2.y);
                    ffma2(acc[j][0], s3, w3.x); ffma2(acc[j][1], s3, w3.y);
                }
            }
            if (warp == 0){
                float4 b4 = *(const float4*)&bg[fo];
                for (int j = 0; j < na; j++){
                    float2 a01 = unpack2(acc[j][0]);
                    float2 a23 = unpack2(acc[j][1]);
                    float4 av = make_float4(a01.x, a01.y, a23.x, a23.y);
                    *(float4*)&g_gate[(size_t)(base+j)*FD + fo] = sigm4(add4(av, b4));
                }
            } else {
                float* dst = (warp == 1) ? g_pi : (warp == 2) ? g_pj : (warp == 3) ? g_pai : g_paj;
                for (int j = 0; j < na; j++){
                    float2 a01 = unpack2(acc[j][0]);
                    float2 a23 = unpack2(acc[j][1]);
                    *(float4*)&dst[(size_t)(base+j)*FD + fo] =
                        make_float4(a01.x, a01.y, a23.x, a23.y);
                }
            }
        }
    }
}

// ------------------- per-block: angle message scatter -----------------------
// Weights held in registers per lane (16 k x 4 cols), pre-packed into k-pair
// u64s so the per-angle loop is pure FFMA2 with naturally-paired angf loads.
__global__ __launch_bounds__(256)
void k_angle(const float* __restrict__ Wang, int A)
{
    const int lane = threadIdx.x & 31;
    const int fo = lane * 4;

    // pack weights: wp[p][c] = (W[2p][fo+c], W[2p+1][fo+c])
    uint64_t wp[8][4];
    #pragma unroll
    for (int p = 0; p < 8; p++){
        float4 we = *(const float4*)&Wang[(2*p  )*FD + fo];
        float4 wo = *(const float4*)&Wang[(2*p+1)*FD + fo];
        wp[p][0] = pack2(we.x, wo.x);
        wp[p][1] = pack2(we.y, wo.y);
        wp[p][2] = pack2(we.z, wo.z);
        wp[p][3] = pack2(we.w, wo.w);
    }

    int gw = (blockIdx.x * blockDim.x + threadIdx.x) >> 5;
    int nw = (gridDim.x * blockDim.x) >> 5;
    for (int a = gw; a < A; a += nw){
        int iij = g_iij[a], kat = g_kat[a];
        const uint64_t* af = (const uint64_t*)&g_angf[(size_t)a*16];
        uint64_t acc[4] = {0ull, 0ull, 0ull, 0ull};
        #pragma unroll
        for (int p = 0; p < 8; p++){
            uint64_t ap = af[p];           // (angf[2p], angf[2p+1]) broadcast
            ffma2(acc[0], ap, wp[p][0]);
            ffma2(acc[1], ap, wp[p][1]);
            ffma2(acc[2], ap, wp[p][2]);
            ffma2(acc[3], ap, wp[p][3]);
        }
        float2 t0 = unpack2(acc[0]), t1 = unpack2(acc[1]);
        float2 t2 = unpack2(acc[2]), t3 = unpack2(acc[3]);
        float4 m = make_float4(t0.x + t0.y, t1.x + t1.y, t2.x + t2.y, t3.x + t3.y);
        float4 g = *(const float4*)&g_gate[(size_t)kat*FD + fo];
        red4(&g_agg[(size_t)iij*FD + fo], mul4(m, g));
    }
}

// ------------------- per-block: fused edge update ---------------------------
// smem: 3x(128x128) W + 2x(5x128) + 3x128 bias + 8 warps x 4 edges x 128 stage
#define SMEM_EDGE_FLOATS (3*FD*FD + 2*5*FD + 3*FD + 8*4*FD)

// packed-f32x2 matvec: acc[j][0] covers outputs fo..fo+1, acc[j][1] fo+2..fo+3
__device__ __forceinline__ void matvec128p(const float* __restrict__ sW,
                                           const float* __restrict__ myst,
                                           int fo, uint64_t acc[4][2])
{
    #pragma unroll 4
    for (int k4 = 0; k4 < 32; k4++){
        ulonglong2 w0 = *(const ulonglong2*)&sW[(k4*4+0)*FD + fo];
        ulonglong2 w1 = *(const ulonglong2*)&sW[(k4*4+1)*FD + fo];
        ulonglong2 w2 = *(const ulonglong2*)&sW[(k4*4+2)*FD + fo];
        ulonglong2 w3 = *(const ulonglong2*)&sW[(k4*4+3)*FD + fo];
        #pragma unroll
        for (int j = 0; j < 4; j++){
            float4 s = *(const float4*)&myst[j*FD + k4*4];
            uint64_t s0 = splat2(s.x), s1 = splat2(s.y);
            uint64_t s2 = splat2(s.z), s3 = splat2(s.w);
            ffma2(acc[j][0], s0, w0.x); ffma2(acc[j][1], s0, w0.y);
            ffma2(acc[j][0], s1, w1.x); ffma2(acc[j][1], s1, w1.y);
            ffma2(acc[j][0], s2, w2.x); ffma2(acc[j][1], s2, w2.y);
            ffma2(acc[j][0], s3, w3.x); ffma2(acc[j][1], s3, w3.y);
        }
    }
}

__device__ __forceinline__ float4 accfold(const uint64_t a[2]){
    float2 a01 = unpack2(a[0]);
    float2 a23 = unpack2(a[1]);
    return make_float4(a01.x, a01.y, a23.x, a23.y);
}

__global__ __launch_bounds__(256, 1)
void k_edge_fused(const float* __restrict__ Wtb,  const float* __restrict__ btb,
                  const float* __restrict__ We1e, const float* __restrict__ be1,
                  const float* __restrict__ We0,
                  const float* __restrict__ Wa1e, const float* __restrict__ ba1,
                  const float* __restrict__ Wa0,
                  const int* __restrict__ edge_index, int E)
{
    extern __shared__ float sm[];
    float* sWtb = sm;
    float* sWe1 = sm + FD*FD;
    float* sWa1 = sm + 2*FD*FD;
    float* sWe0 = sm + 3*FD*FD;
    float* sWa0 = sWe0 + 5*FD;
    float* sbtb = sWa0 + 5*FD;
    float* sbe1 = sbtb + FD;
    float* sba1 = sbe1 + FD;
    float* stg  = sba1 + FD;

    for (int i = threadIdx.x; i < FD*FD/4; i += blockDim.x){
        ((float4*)sWtb)[i] = ((const float4*)Wtb )[i];
        ((float4*)sWe1)[i] = ((const float4*)We1e)[i];
        ((float4*)sWa1)[i] = ((const float4*)Wa1e)[i];
    }
    for (int i = threadIdx.x; i < 5*FD/4; i += blockDim.x){
        ((float4*)sWe0)[i] = ((const float4*)We0)[i];
        ((float4*)sWa0)[i] = ((const float4*)Wa0)[i];
    }
    if (threadIdx.x < FD){
        sbtb[threadIdx.x] = btb[threadIdx.x];
        sbe1[threadIdx.x] = be1[threadIdx.x];
        sba1[threadIdx.x] = ba1[threadIdx.x];
    }
    __syncthreads();

    const int warp = threadIdx.x >> 5;
    const int lane = threadIdx.x & 31;
    const int fo = lane * 4;
    float* myst = stg + warp * 4 * FD;
    const float4 zero4 = make_float4(0,0,0,0);

    for (int base0 = blockIdx.x * 32; base0 < E; base0 += gridDim.x * 32){
        const int base = base0 + warp * 4;
        int ne = E - base; if (ne > 4) ne = 4; if (ne < 0) ne = 0;

        int sendi[4], recvi[4];
        float ef[4][5];
        float4 cur[4];    // running e-vector: e_old -> e1 -> e2
        #pragma unroll
        for (int j = 0; j < 4; j++){
            if (j < ne){
                int eid = base + j;
                sendi[j] = edge_index[eid];
                recvi[j] = edge_index[E + eid];
                #pragma unroll
                for (int n = 0; n < 5; n++) ef[j][n] = g_ef0[(size_t)eid*5 + n];
                *(float4*)&myst[j*FD + fo] = *(const float4*)&g_agg[(size_t)eid*FD + fo];
                // zero agg for the next block's angle scatter (replaces memset)
                *(float4*)&g_agg[(size_t)eid*FD + fo] = zero4;
                cur[j] = *(const float4*)&g_e[(size_t)eid*FD + fo];
            } else {
                sendi[j] = 0; recvi[j] = 0;
                #pragma unroll
                for (int n = 0; n < 5; n++) ef[j][n] = 0.0f;
                cur[j] = zero4;
                *(float4*)&myst[j*FD + fo] = zero4;
            }
        }
        __syncwarp();

        // ---- stage 1: e1 = e + swish(agg @ Wtb + btb)
        uint64_t acc[4][2];
        #pragma unroll
        for (int j = 0; j < 4; j++){ acc[j][0] = 0ull; acc[j][1] = 0ull; }
        matvec128p(sWtb, myst, fo, acc);
        {
            float4 b4 = *(const float4*)&sbtb[fo];
            #pragma unroll
            for (int j = 0; j < 4; j++)
                cur[j] = add4(cur[j], swish4(add4(accfold(acc[j]), b4)));
        }
        __syncwarp();
        #pragma unroll
        for (int j = 0; j < 4; j++) *(float4*)&myst[j*FD + fo] = cur[j];
        __syncwarp();

        // ---- stage 2: e2 = e1 + swish(pi[s] + pj[r] + e1@We1e + be1) * (ef0@We0)
        float4 p0[4];
        #pragma unroll
        for (int j = 0; j < 4; j++) p0[j] = zero4;
        #pragma unroll
        for (int n = 0; n < 5; n++){
            float4 w = *(const float4*)&sWe0[n*FD + fo];
            #pragma unroll
            for (int j = 0; j < 4; j++) fma4(p0[j], ef[j][n], w);
        }
        #pragma unroll
        for (int j = 0; j < 4; j++){ acc[j][0] = 0ull; acc[j][1] = 0ull; }
        matvec128p(sWe1, myst, fo, acc);
        {
            float4 b4 = *(const float4*)&sbe1[fo];
            #pragma unroll
            for (int j = 0; j < 4; j++){
                float4 a = *(const float4*)&g_pi[(size_t)sendi[j]*FD + fo];
                float4 b = *(const float4*)&g_pj[(size_t)recvi[j]*FD + fo];
                float4 pre = add4(accfold(acc[j]),
                                  make_float4(b4.x+a.x+b.x, b4.y+a.y+b.y,
                                              b4.z+a.z+b.z, b4.w+a.w+b.w));
                cur[j] = add4(cur[j], mul4(swish4(pre), p0[j]));
            }
        }
        #pragma unroll
        for (int j = 0; j < 4; j++)
            if (j < ne) *(float4*)&g_e[(size_t)(base+j)*FD + fo] = cur[j];
        __syncwarp();
        #pragma unroll
        for (int j = 0; j < 4; j++) *(float4*)&myst[j*FD + fo] = cur[j];
        __syncwarp();

        // ---- stage 3: v[recv] += swish(pai[s] + paj[r] + e2@Wa1e + ba1) * (ef0@Wa0)
        #pragma unroll
        for (int j = 0; j < 4; j++) p0[j] = zero4;
        #pragma unroll
        for (int n = 0; n < 5; n++){
            float4 w = *(const float4*)&sWa0[n*FD + fo];
            #pragma unroll
            for (int j = 0; j < 4; j++) fma4(p0[j], ef[j][n], w);
        }
        #pragma unroll
        for (int j = 0; j < 4; j++){ acc[j][0] = 0ull; acc[j][1] = 0ull; }
        matvec128p(sWa1, myst, fo, acc);
        {
            float4 b4 = *(const float4*)&sba1[fo];
            #pragma unroll
            for (int j = 0; j < 4; j++){
                if (j < ne){
                    float4 a = *(const float4*)&g_pai[(size_t)sendi[j]*FD + fo];
                    float4 b = *(const float4*)&g_paj[(size_t)recvi[j]*FD + fo];
                    float4 pre = add4(accfold(acc[j]),
                                      make_float4(b4.x+a.x+b.x, b4.y+a.y+b.y,
                                                  b4.z+a.z+b.z, b4.w+a.w+b.w));
                    float4 m = mul4(swish4(pre), p0[j]);
                    red4(&g_v[(size_t)recvi[j]*FD + fo], m);
                }
            }
        }
    }
}

// ------------------- final readout MLP -------------------------------------
__global__ __launch_bounds__(128)
void k_final(const float* __restrict__ W1, const float* __restrict__ b1,
             const float* __restrict__ W2, const float* __restrict__ b2,
             const float* __restrict__ W3, const float* __restrict__ b3,
             float* __restrict__ out, int N)
{
    __shared__ float sv[FD];
    __shared__ float sh[FD];
    __shared__ float sred[4];
    int n = blockIdx.x;
    if (n >= N) return;
    int t = threadIdx.x;
    sv[t] = g_v[(size_t)n*FD + t];
    __syncthreads();
    float acc = b1[t];
    #pragma unroll 8
    for (int k = 0; k < FD; k++) acc = fmaf(sv[k], W1[k*FD + t], acc);
    sh[t] = swishf(acc);
    __syncthreads();
    acc = b2[t];
    #pragma unroll 8
    for (int k = 0; k < FD; k++) acc = fmaf(sh[k], W2[k*FD + t], acc);
    float prod = swishf(acc) * W3[t];
    #pragma unroll
    for (int o = 16; o > 0; o >>= 1) prod += __shfl_down_sync(0xffffffffu, prod, o);
    if ((t & 31) == 0) sred[t >> 5] = prod;
    __syncthreads();
    if (t == 0) out[n] = sred[0] + sred[1] + sred[2] + sred[3] + b3[0];
}

// ------------------------- launch ------------------------------------------
extern "C" void kernel_launch(void* const* d_in, const int* in_sizes, int n_in,
                              void* d_out, int out_size)
{
    const int*   atomic_numbers = (const int*  )d_in[0];
    const int*   edge_index     = (const int*  )d_in[1];
    const float* edge_dist      = (const float*)d_in[2];
    const int*   tbi            = (const int*  )d_in[3];
    const float* norm_ik        = (const float*)d_in[4];
    const float* cos_ang        = (const float*)d_in[5];
    const int*   tnb            = (const int*  )d_in[6];
    const int*   tna            = (const int*  )d_in[7];
    const float* emb            = (const float*)d_in[8];
    const float* W_enc          = (const float*)d_in[9];
    const float* b_enc          = (const float*)d_in[10];
    const float* W_angle        = (const float*)d_in[11];
    const float* Wg             = (const float*)d_in[12];
    const float* bg             = (const float*)d_in[13];
    const float* W_tb           = (const float*)d_in[14];
    const float* b_tb           = (const float*)d_in[15];
    const float* We1            = (const float*)d_in[16];
    const float* be1            = (const float*)d_in[17];
    const float* We0            = (const float*)d_in[18];
    const float* Wa1            = (const float*)d_in[19];
    const float* ba1            = (const float*)d_in[20];
    const float* Wa0            = (const float*)d_in[21];
    const float* W1             = (const float*)d_in[22];
    const float* b1             = (const float*)d_in[23];
    const float* W2             = (const float*)d_in[24];
    const float* b2             = (const float*)d_in[25];
    const float* W3             = (const float*)d_in[26];
    const float* b3             = (const float*)d_in[27];

    const int N = in_sizes[0];           // atoms
    const int E = in_sizes[2];           // edges
    const int A = in_sizes[4];           // angles
    const int G = in_sizes[6];           // graphs
    float* out = (float*)d_out;

    const size_t smem_edge = (size_t)SMEM_EDGE_FLOATS * sizeof(float);
    cudaFuncSetAttribute(k_edge_fused, cudaFuncAttributeMaxDynamicSharedMemorySize, (int)smem_edge);

    float* aggp = nullptr;
    cudaGetSymbolAddress((void**)&aggp, g_agg);

    k_offsets  <<<1, 32>>>(tnb, tna, G);
    k_angle_pre<<<(A + 255) / 256, 256>>>(tbi, norm_ik, cos_ang, edge_index, A, E, G);
    k_edge_init<<<(E + 3) / 4, 128>>>(edge_dist, W_enc, b_enc, E);
    k_vinit    <<<(N * 32 + 255) / 256, 256>>>(atomic_numbers, emb, N);
    cudaMemsetAsync(aggp, 0, (size_t)E * FD * sizeof(float), 0);   // once; edge kernel re-zeros

    for (int b = 0; b < 4; b++){
        k_gate_pre<<<(N + 7) / 8, 256>>>(Wg + (size_t)b*FD*FD, bg + (size_t)b*FD,
                                         We1 + (size_t)b*3*FD*FD, Wa1 + (size_t)b*3*FD*FD, N);
        k_angle<<<1184, 256>>>(W_angle + (size_t)b*16*FD, A);
        k_edge_fused<<<152, 256, smem_edge>>>(
            W_tb + (size_t)b*FD*FD,            b_tb + (size_t)b*FD,
            We1  + (size_t)b*3*FD*FD + 2*FD*FD, be1 + (size_t)b*FD,
            We0  + (size_t)b*5*FD,
            Wa1  + (size_t)b*3*FD*FD + 2*FD*FD, ba1 + (size_t)b*FD,
            Wa0  + (size_t)b*5*FD,
            edge_index, E);
    }

    k_final<<<N, 128>>>(W1, b1, W2, b2, W3, b3, out, N);
}

// round 11
// speedup vs baseline: 1.1072x; 1.1072x over previous
#include <cuda_runtime.h>
#include <math.h>

#define FD   128
#define EMAX 200000
#define NMAX 8000
#define AMAX 400000
#define GMAX 128
#define PI_F 3.14159265358979323846f

// ------------------------- scratch (device globals; no allocs) -------------
__device__ float g_e   [(size_t)EMAX * FD];   // edge features e
__device__ float g_agg [(size_t)EMAX * FD];   // per-block angle aggregation
__device__ float g_ef0 [(size_t)EMAX * 5];    // rbf features (incl sqrt(2/5))
__device__ float g_v   [(size_t)NMAX * FD];   // atom features
__device__ float g_gate[(size_t)NMAX * FD];   // sigmoid(v@Wg+bg) per atom
__device__ float g_pi  [(size_t)NMAX * FD];   // v @ We1[0:128]
__device__ float g_pj  [(size_t)NMAX * FD];   // v @ We1[128:256]
__device__ float g_pai [(size_t)NMAX * FD];   // v @ Wa1[0:128]
__device__ float g_paj [(size_t)NMAX * FD];   // v @ Wa1[128:256]
__device__ float g_angf[(size_t)AMAX * 16];   // rad x P x fc^2
__device__ int   g_iij [AMAX];
__device__ int   g_kat [AMAX];
__device__ int   g_boff[GMAX];
__device__ int   g_acum[GMAX + 1];

// ------------------------- helpers ----------------------------------------
__device__ __forceinline__ void fma4(float4& a, float s, float4 b){
    a.x = fmaf(s, b.x, a.x);
    a.y = fmaf(s, b.y, a.y);
    a.z = fmaf(s, b.z, a.z);
    a.w = fmaf(s, b.w, a.w);
}

__device__ __forceinline__ float sigmf(float x){ return __fdividef(1.0f, 1.0f + __expf(-x)); }
__device__ __forceinline__ float swishf(float x){ return x * sigmf(x); }
__device__ __forceinline__ float4 swish4(float4 a){
    return make_float4(swishf(a.x), swishf(a.y), swishf(a.z), swishf(a.w));
}
__device__ __forceinline__ float4 sigm4(float4 a){
    return make_float4(sigmf(a.x), sigmf(a.y), sigmf(a.z), sigmf(a.w));
}
__device__ __forceinline__ float4 add4(float4 a, float4 b){
    return make_float4(a.x+b.x, a.y+b.y, a.z+b.z, a.w+b.w);
}
__device__ __forceinline__ float4 mul4(float4 a, float4 b){
    return make_float4(a.x*b.x, a.y*b.y, a.z*b.z, a.w*b.w);
}
__device__ __forceinline__ void red4(float* p, float4 v){
    asm volatile("red.global.add.v4.f32 [%0], {%1,%2,%3,%4};"
                 :: "l"(p), "f"(v.x), "f"(v.y), "f"(v.z), "f"(v.w) : "memory");
}

// ------------------------- prep kernels ------------------------------------
__global__ void k_offsets(const int* __restrict__ tnb, const int* __restrict__ tna, int G){
    if (threadIdx.x == 0 && blockIdx.x == 0){
        int ob = 0, oa = 0;
        g_acum[0] = 0;
        for (int g = 0; g < G; g++){
            g_boff[g] = ob;
            ob += tnb[g];
            oa += tna[g];
            g_acum[g + 1] = oa;
        }
    }
}

__global__ void k_angle_pre(const int* __restrict__ tbi,
                            const float* __restrict__ norm_ik,
                            const float* __restrict__ cosang,
                            const int* __restrict__ edge_index,
                            int A, int E, int G)
{
    int a = blockIdx.x * blockDim.x + threadIdx.x;
    if (a >= A) return;
    // find graph: largest g with g_acum[g] <= a
    int lo = 0, hi = G - 1;
    while (lo < hi){ int mid = (lo + hi + 1) >> 1; if (g_acum[mid] <= a) lo = mid; else hi = mid - 1; }
    int off = g_boff[lo];
    int iij = tbi[2*a]     + off;
    int iik = tbi[2*a + 1] + off;
    g_iij[a] = iij;
    g_kat[a] = edge_index[E + iik];         // recv[idx_ik]

    float r = norm_ik[a];
    float c = cosang[a];
    float x = r * 0.25f;                    // r / CUT3
    float x2 = x*x, x3 = x2*x;
    float fc = 1.0f - 6.0f*x3*x2 + 15.0f*x2*x2 - 10.0f*x3;
    float invr = 1.0f / r;
    float s2 = fc * fc * invr;              // fold 1/r + fc^2 (one fc from shrb, one from msg)
    float rad[4];
    #pragma unroll
    for (int n = 0; n < 4; n++) rad[n] = sinf((float)(n+1) * PI_F * x) * s2;
    float P0 = 1.0f, P1 = c;
    float P2 = 0.5f * (3.0f*c*c - 1.0f);
    float P3 = 0.5f * c * (5.0f*c*c - 3.0f);
    #pragma unroll
    for (int n = 0; n < 4; n++)
        *(float4*)&g_angf[(size_t)a*16 + n*4] = make_float4(rad[n]*P0, rad[n]*P1, rad[n]*P2, rad[n]*P3);
}

__global__ void k_edge_init(const float* __restrict__ edge_dist,
                            const float* __restrict__ W_enc,
                            const float* __restrict__ b_enc, int E)
{
    int gw   = (blockIdx.x * blockDim.x + threadIdx.x) >> 5;
    int lane = threadIdx.x & 31;
    if (gw >= E) return;
    float r    = edge_dist[gw];
    float invr = 1.0f / r;
    const float C = sqrtf(2.0f / 5.0f);
    float ef[5];
    #pragma unroll
    for (int n = 0; n < 5; n++) ef[n] = C * sinf((float)(n+1) * PI_F * r * 0.2f) * invr;
    if (lane < 5) g_ef0[(size_t)gw*5 + lane] = ef[lane];
    int fo = lane * 4;
    float4 acc = *(const float4*)&b_enc[fo];
    #pragma unroll
    for (int n = 0; n < 5; n++){
        float4 w = *(const float4*)&W_enc[n*FD + fo];
        fma4(acc, ef[n], w);
    }
    *(float4*)&g_e[(size_t)gw*FD + fo] = swish4(acc);
}

__global__ void k_vinit(const int* __restrict__ z, const float* __restrict__ emb, int N){
    int t = blockIdx.x * blockDim.x + threadIdx.x;
    if (t >= N * 32) return;
    int n = t >> 5, fo = (t & 31) * 4;
    *(float4*)&g_v[(size_t)n*FD + fo] = *(const float4*)&emb[(size_t)z[n]*FD + fo];
}

// ------------------- per-block: atom precompute (gate + concat parts) -------
__global__ __launch_bounds__(256)
void k_gate_pre(const float* __restrict__ Wg,  const float* __restrict__ bg,
                const float* __restrict__ We1b, const float* __restrict__ Wa1b, int N)
{
    __shared__ float sv[8][FD];
    const int warp = threadIdx.x >> 5, lane = threadIdx.x & 31;
    const int fo = lane * 4;
    for (int base = blockIdx.x * 8; base < N; base += gridDim.x * 8){
        int na = N - base; if (na > 8) na = 8;
        __syncthreads();
        for (int idx = threadIdx.x; idx < na * 32; idx += blockDim.x){
            int rr = idx >> 5, cc = (idx & 31) * 4;
            *(float4*)&sv[rr][cc] = *(const float4*)&g_v[(size_t)(base+rr)*FD + cc];
        }
        __syncthreads();
        if (warp < 5){
            const float* W = (warp == 0) ? Wg
                           : (warp == 1) ? We1b
                           : (warp == 2) ? (We1b + FD*FD)
                           : (warp == 3) ? Wa1b
                           :               (Wa1b + FD*FD);
            float4 acc[8];
            #pragma unroll
            for (int j = 0; j < 8; j++) acc[j] = make_float4(0,0,0,0);
            #pragma unroll 4
            for (int k4 = 0; k4 < 32; k4++){
                float4 w0 = *(const float4*)&W[(k4*4+0)*FD + fo];
                float4 w1 = *(const float4*)&W[(k4*4+1)*FD + fo];
                float4 w2 = *(const float4*)&W[(k4*4+2)*FD + fo];
                float4 w3 = *(const float4*)&W[(k4*4+3)*FD + fo];
                #pragma unroll
                for (int j = 0; j < 8; j++){
                    float4 s = *(const float4*)&sv[j][k4*4];
                    fma4(acc[j], s.x, w0); fma4(acc[j], s.y, w1);
                    fma4(acc[j], s.z, w2); fma4(acc[j], s.w, w3);
                }
            }
            if (warp == 0){
                float4 b4 = *(const float4*)&bg[fo];
                for (int j = 0; j < na; j++)
                    *(float4*)&g_gate[(size_t)(base+j)*FD + fo] = sigm4(add4(acc[j], b4));
            } else {
                float* dst = (warp == 1) ? g_pi : (warp == 2) ? g_pj : (warp == 3) ? g_pai : g_paj;
                for (int j = 0; j < na; j++)
                    *(float4*)&dst[(size_t)(base+j)*FD + fo] = acc[j];
            }
        }
    }
}

// ------------------- per-block: angle message scatter -----------------------
// Weight tile (16 x 128) held in registers: 64 floats per lane (lane covers
// output cols fo..fo+3). Removes all smem crossbar traffic from the hot loop.
__global__ __launch_bounds__(256)
void k_angle(const float* __restrict__ Wang, int A)
{
    const int lane = threadIdx.x & 31;
    const int fo = lane * 4;

    float4 wr[16];
    #pragma unroll
    for (int k = 0; k < 16; k++)
        wr[k] = *(const float4*)&Wang[k*FD + fo];

    int gw = (blockIdx.x * blockDim.x + threadIdx.x) >> 5;
    int nw = (gridDim.x * blockDim.x) >> 5;
    for (int a = gw; a < A; a += nw){
        int iij = g_iij[a], kat = g_kat[a];
        const float4* af = (const float4*)&g_angf[(size_t)a*16];
        float4 acc = make_float4(0,0,0,0);
        #pragma unroll
        for (int k4 = 0; k4 < 4; k4++){
            float4 s = af[k4];
            fma4(acc, s.x, wr[k4*4+0]);
            fma4(acc, s.y, wr[k4*4+1]);
            fma4(acc, s.z, wr[k4*4+2]);
            fma4(acc, s.w, wr[k4*4+3]);
        }
        float4 g = *(const float4*)&g_gate[(size_t)kat*FD + fo];
        red4(&g_agg[(size_t)iij*FD + fo], mul4(acc, g));
    }
}

// ------------------- per-block: fused edge update ---------------------------
// smem: 3x(128x128) W + 2x(5x128) + 3x128 bias + 8 warps x 4 edges x 128 stage
#define SMEM_EDGE_FLOATS (3*FD*FD + 2*5*FD + 3*FD + 8*4*FD)

__device__ __forceinline__ void matvec128(const float* __restrict__ sW,
                                          const float* __restrict__ myst,
                                          int fo, float4 acc[4])
{
    #pragma unroll 4
    for (int k4 = 0; k4 < 32; k4++){
        float4 w0 = *(const float4*)&sW[(k4*4+0)*FD + fo];
        float4 w1 = *(const float4*)&sW[(k4*4+1)*FD + fo];
        float4 w2 = *(const float4*)&sW[(k4*4+2)*FD + fo];
        float4 w3 = *(const float4*)&sW[(k4*4+3)*FD + fo];
        #pragma unroll
        for (int j = 0; j < 4; j++){
            float4 s = *(const float4*)&myst[j*FD + k4*4];
            fma4(acc[j], s.x, w0); fma4(acc[j], s.y, w1);
            fma4(acc[j], s.z, w2); fma4(acc[j], s.w, w3);
        }
    }
}

__global__ __launch_bounds__(256, 1)
void k_edge_fused(const float* __restrict__ Wtb,  const float* __restrict__ btb,
                  const float* __restrict__ We1e, const float* __restrict__ be1,
                  const float* __restrict__ We0,
                  const float* __restrict__ Wa1e, const float* __restrict__ ba1,
                  const float* __restrict__ Wa0,
                  const int* __restrict__ edge_index, int E)
{
    extern __shared__ float sm[];
    float* sWtb = sm;
    float* sWe1 = sm + FD*FD;
    float* sWa1 = sm + 2*FD*FD;
    float* sWe0 = sm + 3*FD*FD;
    float* sWa0 = sWe0 + 5*FD;
    float* sbtb = sWa0 + 5*FD;
    float* sbe1 = sbtb + FD;
    float* sba1 = sbe1 + FD;
    float* stg  = sba1 + FD;

    for (int i = threadIdx.x; i < FD*FD/4; i += blockDim.x){
        ((float4*)sWtb)[i] = ((const float4*)Wtb )[i];
        ((float4*)sWe1)[i] = ((const float4*)We1e)[i];
        ((float4*)sWa1)[i] = ((const float4*)Wa1e)[i];
    }
    for (int i = threadIdx.x; i < 5*FD/4; i += blockDim.x){
        ((float4*)sWe0)[i] = ((const float4*)We0)[i];
        ((float4*)sWa0)[i] = ((const float4*)Wa0)[i];
    }
    if (threadIdx.x < FD){
        sbtb[threadIdx.x] = btb[threadIdx.x];
        sbe1[threadIdx.x] = be1[threadIdx.x];
        sba1[threadIdx.x] = ba1[threadIdx.x];
    }
    __syncthreads();

    const int warp = threadIdx.x >> 5;
    const int lane = threadIdx.x & 31;
    const int fo = lane * 4;
    float* myst = stg + warp * 4 * FD;
    const float4 zero4 = make_float4(0,0,0,0);

    for (int base0 = blockIdx.x * 32; base0 < E; base0 += gridDim.x * 32){
        const int base = base0 + warp * 4;
        int ne = E - base; if (ne > 4) ne = 4; if (ne < 0) ne = 0;

        int sendi[4], recvi[4];
        float ef[4][5];
        float4 cur[4];    // running e-vector: e_old -> e1 -> e2
        #pragma unroll
        for (int j = 0; j < 4; j++){
            if (j < ne){
                int eid = base + j;
                sendi[j] = edge_index[eid];
                recvi[j] = edge_index[E + eid];
                #pragma unroll
                for (int n = 0; n < 5; n++) ef[j][n] = g_ef0[(size_t)eid*5 + n];
                *(float4*)&myst[j*FD + fo] = *(const float4*)&g_agg[(size_t)eid*FD + fo];
                // zero agg for the next block's angle scatter (replaces memset)
                *(float4*)&g_agg[(size_t)eid*FD + fo] = zero4;
                cur[j] = *(const float4*)&g_e[(size_t)eid*FD + fo];
            } else {
                sendi[j] = 0; recvi[j] = 0;
                #pragma unroll
                for (int n = 0; n < 5; n++) ef[j][n] = 0.0f;
                cur[j] = zero4;
                *(float4*)&myst[j*FD + fo] = zero4;
            }
        }
        __syncwarp();

        // ---- stage 1: e1 = e + swish(agg @ Wtb + btb)
        float4 acc[4];
        {
            float4 b4 = *(const float4*)&sbtb[fo];
            #pragma unroll
            for (int j = 0; j < 4; j++) acc[j] = b4;
        }
        matvec128(sWtb, myst, fo, acc);
        #pragma unroll
        for (int j = 0; j < 4; j++) cur[j] = add4(cur[j], swish4(acc[j]));
        __syncwarp();
        #pragma unroll
        for (int j = 0; j < 4; j++) *(float4*)&myst[j*FD + fo] = cur[j];
        __syncwarp();

        // ---- stage 2: e2 = e1 + swish(pi[s] + pj[r] + e1@We1e + be1) * (ef0@We0)
        float4 p0[4];
        #pragma unroll
        for (int j = 0; j < 4; j++) p0[j] = zero4;
        #pragma unroll
        for (int n = 0; n < 5; n++){
            float4 w = *(const float4*)&sWe0[n*FD + fo];
            #pragma unroll
            for (int j = 0; j < 4; j++) fma4(p0[j], ef[j][n], w);
        }
        {
            float4 b4 = *(const float4*)&sbe1[fo];
            #pragma unroll
            for (int j = 0; j < 4; j++){
                float4 a = *(const float4*)&g_pi[(size_t)sendi[j]*FD + fo];
                float4 b = *(const float4*)&g_pj[(size_t)recvi[j]*FD + fo];
                acc[j] = make_float4(b4.x+a.x+b.x, b4.y+a.y+b.y, b4.z+a.z+b.z, b4.w+a.w+b.w);
            }
        }
        matvec128(sWe1, myst, fo, acc);
        #pragma unroll
        for (int j = 0; j < 4; j++) cur[j] = add4(cur[j], mul4(swish4(acc[j]), p0[j]));
        #pragma unroll
        for (int j = 0; j < 4; j++)
            if (j < ne) *(float4*)&g_e[(size_t)(base+j)*FD + fo] = cur[j];
        __syncwarp();
        #pragma unroll
        for (int j = 0; j < 4; j++) *(float4*)&myst[j*FD + fo] = cur[j];
        __syncwarp();

        // ---- stage 3: v[recv] += swish(pai[s] + paj[r] + e2@Wa1e + ba1) * (ef0@Wa0)
        #pragma unroll
        for (int j = 0; j < 4; j++) p0[j] = zero4;
        #pragma unroll
        for (int n = 0; n < 5; n++){
            float4 w = *(const float4*)&sWa0[n*FD + fo];
            #pragma unroll
            for (int j = 0; j < 4; j++) fma4(p0[j], ef[j][n], w);
        }
        {
            float4 b4 = *(const float4*)&sba1[fo];
            #pragma unroll
            for (int j = 0; j < 4; j++){
                float4 a = *(const float4*)&g_pai[(size_t)sendi[j]*FD + fo];
                float4 b = *(const float4*)&g_paj[(size_t)recvi[j]*FD + fo];
                acc[j] = make_float4(b4.x+a.x+b.x, b4.y+a.y+b.y, b4.z+a.z+b.z, b4.w+a.w+b.w);
            }
        }
        matvec128(sWa1, myst, fo, acc);
        #pragma unroll
        for (int j = 0; j < 4; j++){
            if (j < ne){
                float4 m = mul4(swish4(acc[j]), p0[j]);
                red4(&g_v[(size_t)recvi[j]*FD + fo], m);
            }
        }
    }
}

// ------------------- final readout MLP -------------------------------------
__global__ __launch_bounds__(128)
void k_final(const float* __restrict__ W1, const float* __restrict__ b1,
             const float* __restrict__ W2, const float* __restrict__ b2,
             const float* __restrict__ W3, const float* __restrict__ b3,
             float* __restrict__ out, int N)
{
    __shared__ float sv[FD];
    __shared__ float sh[FD];
    __shared__ float sred[4];
    int n = blockIdx.x;
    if (n >= N) return;
    int t = threadIdx.x;
    sv[t] = g_v[(size_t)n*FD + t];
    __syncthreads();
    float acc = b1[t];
    #pragma unroll 8
    for (int k = 0; k < FD; k++) acc = fmaf(sv[k], W1[k*FD + t], acc);
    sh[t] = swishf(acc);
    __syncthreads();
    acc = b2[t];
    #pragma unroll 8
    for (int k = 0; k < FD; k++) acc = fmaf(sh[k], W2[k*FD + t], acc);
    float prod = swishf(acc) * W3[t];
    #pragma unroll
    for (int o = 16; o > 0; o >>= 1) prod += __shfl_down_sync(0xffffffffu, prod, o);
    if ((t & 31) == 0) sred[t >> 5] = prod;
    __syncthreads();
    if (t == 0) out[n] = sred[0] + sred[1] + sred[2] + sred[3] + b3[0];
}

// ------------------------- launch ------------------------------------------
extern "C" void kernel_launch(void* const* d_in, const int* in_sizes, int n_in,
                              void* d_out, int out_size)
{
    const int*   atomic_numbers = (const int*  )d_in[0];
    const int*   edge_index     = (const int*  )d_in[1];
    const float* edge_dist      = (const float*)d_in[2];
    const int*   tbi            = (const int*  )d_in[3];
    const float* norm_ik        = (const float*)d_in[4];
    const float* cos_ang        = (const float*)d_in[5];
    const int*   tnb            = (const int*  )d_in[6];
    const int*   tna            = (const int*  )d_in[7];
    const float* emb            = (const float*)d_in[8];
    const float* W_enc          = (const float*)d_in[9];
    const float* b_enc          = (const float*)d_in[10];
    const float* W_angle        = (const float*)d_in[11];
    const float* Wg             = (const float*)d_in[12];
    const float* bg             = (const float*)d_in[13];
    const float* W_tb           = (const float*)d_in[14];
    const float* b_tb           = (const float*)d_in[15];
    const float* We1            = (const float*)d_in[16];
    const float* be1            = (const float*)d_in[17];
    const float* We0            = (const float*)d_in[18];
    const float* Wa1            = (const float*)d_in[19];
    const float* ba1            = (const float*)d_in[20];
    const float* Wa0            = (const float*)d_in[21];
    const float* W1             = (const float*)d_in[22];
    const float* b1             = (const float*)d_in[23];
    const float* W2             = (const float*)d_in[24];
    const float* b2             = (const float*)d_in[25];
    const float* W3             = (const float*)d_in[26];
    const float* b3             = (const float*)d_in[27];

    const int N = in_sizes[0];           // atoms
    const int E = in_sizes[2];           // edges
    const int A = in_sizes[4];           // angles
    const int G = in_sizes[6];           // graphs
    float* out = (float*)d_out;

    const size_t smem_edge = (size_t)SMEM_EDGE_FLOATS * sizeof(float);
    cudaFuncSetAttribute(k_edge_fused, cudaFuncAttributeMaxDynamicSharedMemorySize, (int)smem_edge);

    float* aggp = nullptr;
    cudaGetSymbolAddress((void**)&aggp, g_agg);

    k_offsets  <<<1, 32>>>(tnb, tna, G);
    k_angle_pre<<<(A + 255) / 256, 256>>>(tbi, norm_ik, cos_ang, edge_index, A, E, G);
    k_edge_init<<<(E + 3) / 4, 128>>>(edge_dist, W_enc, b_enc, E);
    k_vinit    <<<(N * 32 + 255) / 256, 256>>>(atomic_numbers, emb, N);
    cudaMemsetAsync(aggp, 0, (size_t)E * FD * sizeof(float), 0);   // once; edge kernel re-zeros

    for (int b = 0; b < 4; b++){
        k_gate_pre<<<(N + 7) / 8, 256>>>(Wg + (size_t)b*FD*FD, bg + (size_t)b*FD,
                                         We1 + (size_t)b*3*FD*FD, Wa1 + (size_t)b*3*FD*FD, N);
        k_angle<<<1184, 256>>>(W_angle + (size_t)b*16*FD, A);
        k_edge_fused<<<152, 256, smem_edge>>>(
            W_tb + (size_t)b*FD*FD,            b_tb + (size_t)b*FD,
            We1  + (size_t)b*3*FD*FD + 2*FD*FD, be1 + (size_t)b*FD,
            We0  + (size_t)b*5*FD,
            Wa1  + (size_t)b*3*FD*FD + 2*FD*FD, ba1 + (size_t)b*FD,
            Wa0  + (size_t)b*5*FD,
            edge_index, E);
    }

    k_final<<<N, 128>>>(W1, b1, W2, b2, W3, b3, out, N);
}

// round 12
// speedup vs baseline: 1.2138x; 1.0963x over previous
#include <cuda_runtime.h>
#include <math.h>
#include <stdint.h>

#define FD   128
#define EMAX 200000
#define NMAX 8000
#define AMAX 400000
#define GMAX 128
#define PI_F 3.14159265358979323846f

// ------------------------- scratch (device globals; no allocs) -------------
__device__ float g_e   [(size_t)EMAX * FD];
__device__ float g_agg [(size_t)EMAX * FD];
__device__ float g_ef0 [(size_t)EMAX * 5];
__device__ float g_v   [(size_t)NMAX * FD];
__device__ float g_gate[(size_t)NMAX * FD];
__device__ float g_pi  [(size_t)NMAX * FD];
__device__ float g_pj  [(size_t)NMAX * FD];
__device__ float g_pai [(size_t)NMAX * FD];
__device__ float g_paj [(size_t)NMAX * FD];
__device__ float g_angf[(size_t)AMAX * 16];
__device__ int   g_iij [AMAX];
__device__ int   g_kat [AMAX];
__device__ int   g_boff[GMAX];
__device__ int   g_acum[GMAX + 1];

// ------------------------- helpers ----------------------------------------
__device__ __forceinline__ void fma4(float4& a, float s, float4 b){
    a.x = fmaf(s, b.x, a.x);
    a.y = fmaf(s, b.y, a.y);
    a.z = fmaf(s, b.z, a.z);
    a.w = fmaf(s, b.w, a.w);
}
__device__ __forceinline__ float sigmf(float x){ return __fdividef(1.0f, 1.0f + __expf(-x)); }
__device__ __forceinline__ float swishf(float x){ return x * sigmf(x); }
__device__ __forceinline__ float4 swish4(float4 a){
    return make_float4(swishf(a.x), swishf(a.y), swishf(a.z), swishf(a.w));
}
__device__ __forceinline__ float4 sigm4(float4 a){
    return make_float4(sigmf(a.x), sigmf(a.y), sigmf(a.z), sigmf(a.w));
}
__device__ __forceinline__ float4 add4(float4 a, float4 b){
    return make_float4(a.x+b.x, a.y+b.y, a.z+b.z, a.w+b.w);
}
__device__ __forceinline__ float4 mul4(float4 a, float4 b){
    return make_float4(a.x*b.x, a.y*b.y, a.z*b.z, a.w*b.w);
}
__device__ __forceinline__ void red4(float* p, float4 v){
    asm volatile("red.global.add.v4.f32 [%0], {%1,%2,%3,%4};"
                 :: "l"(p), "f"(v.x), "f"(v.y), "f"(v.z), "f"(v.w) : "memory");
}
__device__ __forceinline__ uint32_t f2tf(float x){
    uint32_t u; asm("cvt.rna.tf32.f32 %0, %1;" : "=r"(u) : "f"(x)); return u;
}
__device__ __forceinline__ void mma_tf32(float c[4],
    uint32_t a0, uint32_t a1, uint32_t a2, uint32_t a3,
    uint32_t b0, uint32_t b1)
{
    asm volatile(
        "mma.sync.aligned.m16n8k8.row.col.f32.tf32.tf32.f32 "
        "{%0,%1,%2,%3}, {%4,%5,%6,%7}, {%8,%9}, {%0,%1,%2,%3};"
        : "+f"(c[0]), "+f"(c[1]), "+f"(c[2]), "+f"(c[3])
        : "r"(a0), "r"(a1), "r"(a2), "r"(a3), "r"(b0), "r"(b1));
}

// ------------------------- prep kernels ------------------------------------
__global__ void k_offsets(const int* __restrict__ tnb, const int* __restrict__ tna, int G){
    if (threadIdx.x == 0 && blockIdx.x == 0){
        int ob = 0, oa = 0;
        g_acum[0] = 0;
        for (int g = 0; g < G; g++){
            g_boff[g] = ob;
            ob += tnb[g];
            oa += tna[g];
            g_acum[g + 1] = oa;
        }
    }
}

__global__ void k_angle_pre(const int* __restrict__ tbi,
                            const float* __restrict__ norm_ik,
                            const float* __restrict__ cosang,
                            const int* __restrict__ edge_index,
                            int A, int E, int G)
{
    int a = blockIdx.x * blockDim.x + threadIdx.x;
    if (a >= A) return;
    int lo = 0, hi = G - 1;
    while (lo < hi){ int mid = (lo + hi + 1) >> 1; if (g_acum[mid] <= a) lo = mid; else hi = mid - 1; }
    int off = g_boff[lo];
    int iij = tbi[2*a]     + off;
    int iik = tbi[2*a + 1] + off;
    g_iij[a] = iij;
    g_kat[a] = edge_index[E + iik];

    float r = norm_ik[a];
    float c = cosang[a];
    float x = r * 0.25f;
    float x2 = x*x, x3 = x2*x;
    float fc = 1.0f - 6.0f*x3*x2 + 15.0f*x2*x2 - 10.0f*x3;
    float invr = 1.0f / r;
    float s2 = fc * fc * invr;
    float rad[4];
    #pragma unroll
    for (int n = 0; n < 4; n++) rad[n] = sinf((float)(n+1) * PI_F * x) * s2;
    float P0 = 1.0f, P1 = c;
    float P2 = 0.5f * (3.0f*c*c - 1.0f);
    float P3 = 0.5f * c * (5.0f*c*c - 3.0f);
    #pragma unroll
    for (int n = 0; n < 4; n++)
        *(float4*)&g_angf[(size_t)a*16 + n*4] = make_float4(rad[n]*P0, rad[n]*P1, rad[n]*P2, rad[n]*P3);
}

__global__ void k_edge_init(const float* __restrict__ edge_dist,
                            const float* __restrict__ W_enc,
                            const float* __restrict__ b_enc, int E)
{
    int gw   = (blockIdx.x * blockDim.x + threadIdx.x) >> 5;
    int lane = threadIdx.x & 31;
    if (gw >= E) return;
    float r    = edge_dist[gw];
    float invr = 1.0f / r;
    const float C = sqrtf(2.0f / 5.0f);
    float ef[5];
    #pragma unroll
    for (int n = 0; n < 5; n++) ef[n] = C * sinf((float)(n+1) * PI_F * r * 0.2f) * invr;
    if (lane < 5) g_ef0[(size_t)gw*5 + lane] = ef[lane];
    int fo = lane * 4;
    float4 acc = *(const float4*)&b_enc[fo];
    #pragma unroll
    for (int n = 0; n < 5; n++){
        float4 w = *(const float4*)&W_enc[n*FD + fo];
        fma4(acc, ef[n], w);
    }
    *(float4*)&g_e[(size_t)gw*FD + fo] = swish4(acc);
}

__global__ void k_vinit(const int* __restrict__ z, const float* __restrict__ emb, int N){
    int t = blockIdx.x * blockDim.x + threadIdx.x;
    if (t >= N * 32) return;
    int n = t >> 5, fo = (t & 31) * 4;
    *(float4*)&g_v[(size_t)n*FD + fo] = *(const float4*)&emb[(size_t)z[n]*FD + fo];
}

// ------------------- per-block: atom precompute (gate + concat parts) -------
__global__ __launch_bounds__(256)
void k_gate_pre(const float* __restrict__ Wg,  const float* __restrict__ bg,
                const float* __restrict__ We1b, const float* __restrict__ Wa1b, int N)
{
    __shared__ float sv[8][FD];
    const int warp = threadIdx.x >> 5, lane = threadIdx.x & 31;
    const int fo = lane * 4;
    for (int base = blockIdx.x * 8; base < N; base += gridDim.x * 8){
        int na = N - base; if (na > 8) na = 8;
        __syncthreads();
        for (int idx = threadIdx.x; idx < na * 32; idx += blockDim.x){
            int rr = idx >> 5, cc = (idx & 31) * 4;
            *(float4*)&sv[rr][cc] = *(const float4*)&g_v[(size_t)(base+rr)*FD + cc];
        }
        __syncthreads();
        if (warp < 5){
            const float* W = (warp == 0) ? Wg
                           : (warp == 1) ? We1b
                           : (warp == 2) ? (We1b + FD*FD)
                           : (warp == 3) ? Wa1b
                           :               (Wa1b + FD*FD);
            float4 acc[8];
            #pragma unroll
            for (int j = 0; j < 8; j++) acc[j] = make_float4(0,0,0,0);
            #pragma unroll 4
            for (int k4 = 0; k4 < 32; k4++){
                float4 w0 = *(const float4*)&W[(k4*4+0)*FD + fo];
                float4 w1 = *(const float4*)&W[(k4*4+1)*FD + fo];
                float4 w2 = *(const float4*)&W[(k4*4+2)*FD + fo];
                float4 w3 = *(const float4*)&W[(k4*4+3)*FD + fo];
                #pragma unroll
                for (int j = 0; j < 8; j++){
                    float4 s = *(const float4*)&sv[j][k4*4];
                    fma4(acc[j], s.x, w0); fma4(acc[j], s.y, w1);
                    fma4(acc[j], s.z, w2); fma4(acc[j], s.w, w3);
                }
            }
            if (warp == 0){
                float4 b4 = *(const float4*)&bg[fo];
                for (int j = 0; j < na; j++)
                    *(float4*)&g_gate[(size_t)(base+j)*FD + fo] = sigm4(add4(acc[j], b4));
            } else {
                float* dst = (warp == 1) ? g_pi : (warp == 2) ? g_pj : (warp == 3) ? g_pai : g_paj;
                for (int j = 0; j < na; j++)
                    *(float4*)&dst[(size_t)(base+j)*FD + fo] = acc[j];
            }
        }
    }
}

// ------------------- per-block: angle message scatter (R9 version) ----------
__global__ __launch_bounds__(256)
void k_angle(const float* __restrict__ Wang, int A)
{
    __shared__ float sW[16 * FD];
    for (int i = threadIdx.x; i < 16*FD/4; i += blockDim.x)
        ((float4*)sW)[i] = ((const float4*)Wang)[i];
    __syncthreads();
    const int lane = threadIdx.x & 31;
    const int fo = lane * 4;
    int gw = (blockIdx.x * blockDim.x + threadIdx.x) >> 5;
    int nw = (gridDim.x * blockDim.x) >> 5;
    for (int a = gw; a < A; a += nw){
        int iij = g_iij[a], kat = g_kat[a];
        const float4* af = (const float4*)&g_angf[(size_t)a*16];
        float4 acc = make_float4(0,0,0,0);
        #pragma unroll
        for (int k4 = 0; k4 < 4; k4++){
            float4 s  = af[k4];
            float4 w0 = *(const float4*)&sW[(k4*4+0)*FD + fo];
            float4 w1 = *(const float4*)&sW[(k4*4+1)*FD + fo];
            float4 w2 = *(const float4*)&sW[(k4*4+2)*FD + fo];
            float4 w3 = *(const float4*)&sW[(k4*4+3)*FD + fo];
            fma4(acc, s.x, w0); fma4(acc, s.y, w1); fma4(acc, s.z, w2); fma4(acc, s.w, w3);
        }
        float4 g = *(const float4*)&g_gate[(size_t)kat*FD + fo];
        red4(&g_agg[(size_t)iij*FD + fo], mul4(acc, g));
    }
}

// ------------------- per-block: fused edge update, tf32 tensor cores --------
// 4 warps, 16 edges per CTA iteration.
// smem: 3 weight matrices in tf32 (XOR-swizzled), A tile (tf32, swizzled),
// D staging buffer (fp32, swizzled), plus fp32 epilogue constants.
#define TILE_E 16
#define SMEM_EDGE_BYTES ((3*16384 + 2048 + 2048 + 2*5*FD + 3*FD) * 4)

// GEMM: D[16 x 128] = A[16 x 128] @ W[128 x 128]; warp handles 4 n8 coltiles.
__device__ __forceinline__ void gemm_stage(const uint32_t* __restrict__ sW,
                                           const uint32_t* __restrict__ sA,
                                           float* __restrict__ sD,
                                           int warp, int lane)
{
    const int gid = lane >> 2;          // 0..7
    const int t   = lane & 3;           // 0..3
    const int r0  = gid, r1 = gid + 8;
    const int sz0 = (r0 & 3) * 8, sz1 = (r1 & 3) * 8;
    float c[4][4];
    #pragma unroll
    for (int i = 0; i < 4; i++){ c[i][0]=0.f; c[i][1]=0.f; c[i][2]=0.f; c[i][3]=0.f; }

    #pragma unroll
    for (int ks = 0; ks < 16; ks++){
        const int k0 = ks*8 + t;
        uint32_t a0 = sA[r0*128 + ((k0    ) ^ sz0)];
        uint32_t a1 = sA[r1*128 + ((k0    ) ^ sz1)];
        uint32_t a2 = sA[r0*128 + ((k0 + 4) ^ sz0)];
        uint32_t a3 = sA[r1*128 + ((k0 + 4) ^ sz1)];
        #pragma unroll
        for (int i = 0; i < 4; i++){
            const int col = (warp*4 + i)*8 + gid;
            uint32_t b0 = sW[(k0    )*128 + (col ^ (t*8))];
            uint32_t b1 = sW[(k0 + 4)*128 + (col ^ (t*8))];
            mma_tf32(c[i], a0, a1, a2, a3, b0, b1);
        }
    }
    #pragma unroll
    for (int i = 0; i < 4; i++){
        const int colb = (warp*4 + i)*8 + 2*t;
        *(float2*)&sD[r0*128 + (colb ^ sz0)] = make_float2(c[i][0], c[i][1]);
        *(float2*)&sD[r1*128 + (colb ^ sz1)] = make_float2(c[i][2], c[i][3]);
    }
}

__device__ __forceinline__ void stA_tf32(uint32_t* __restrict__ sA, int row, int fo, float4 v){
    uint4 u = make_uint4(f2tf(v.x), f2tf(v.y), f2tf(v.z), f2tf(v.w));
    *(uint4*)&sA[row*128 + (fo ^ ((row & 3)*8))] = u;
}
__device__ __forceinline__ float4 ldD(const float* __restrict__ sD, int row, int fo){
    return *(const float4*)&sD[row*128 + (fo ^ ((row & 3)*8))];
}

__global__ __launch_bounds__(128, 1)
void k_edge_fused(const float* __restrict__ Wtb,  const float* __restrict__ btb,
                  const float* __restrict__ We1e, const float* __restrict__ be1,
                  const float* __restrict__ We0,
                  const float* __restrict__ Wa1e, const float* __restrict__ ba1,
                  const float* __restrict__ Wa0,
                  const int* __restrict__ edge_index, int E)
{
    extern __shared__ char smraw[];
    uint32_t* sWtb = (uint32_t*)smraw;
    uint32_t* sWe1 = sWtb + 16384;
    uint32_t* sWa1 = sWe1 + 16384;
    uint32_t* sAu  = sWa1 + 16384;           // 16 x 128
    float*    sD   = (float*)(sAu + 2048);   // 16 x 128
    float*    sWe0 = sD + 2048;
    float*    sWa0 = sWe0 + 5*FD;
    float*    sbtb = sWa0 + 5*FD;
    float*    sbe1 = sbtb + FD;
    float*    sba1 = sbe1 + FD;

    // load + tf32-convert + swizzle weights (k-row major, col ^ 8*(k&3))
    for (int i = threadIdx.x; i < FD*FD; i += blockDim.x){
        int k = i >> 7, col = i & 127;
        int dst = k*128 + (col ^ ((k & 3)*8));
        sWtb[dst] = f2tf(Wtb [i]);
        sWe1[dst] = f2tf(We1e[i]);
        sWa1[dst] = f2tf(Wa1e[i]);
    }
    for (int i = threadIdx.x; i < 5*FD; i += blockDim.x){
        sWe0[i] = We0[i];
        sWa0[i] = Wa0[i];
    }
    if (threadIdx.x < FD){
        sbtb[threadIdx.x] = btb[threadIdx.x];
        sbe1[threadIdx.x] = be1[threadIdx.x];
        sba1[threadIdx.x] = ba1[threadIdx.x];
    }
    __syncthreads();

    const int warp = threadIdx.x >> 5;
    const int lane = threadIdx.x & 31;
    const int fo = lane * 4;
    const float4 zero4 = make_float4(0,0,0,0);

    for (int base0 = blockIdx.x * TILE_E; base0 < E; base0 += gridDim.x * TILE_E){
        const int base = base0 + warp * 4;   // warp owns 4 edges (rows warp*4..+3)

        int sendi[4], recvi[4];
        bool ok[4];
        float ef[4][5];
        float4 cur[4];
        #pragma unroll
        for (int j = 0; j < 4; j++){
            const int row = warp*4 + j;
            const int eid = base + j;
            ok[j] = (eid < E);
            if (ok[j]){
                sendi[j] = edge_index[eid];
                recvi[j] = edge_index[E + eid];
                #pragma unroll
                for (int n = 0; n < 5; n++) ef[j][n] = g_ef0[(size_t)eid*5 + n];
                float4 a = *(const float4*)&g_agg[(size_t)eid*FD + fo];
                cur[j] = *(const float4*)&g_e[(size_t)eid*FD + fo];
                stA_tf32(sAu, row, fo, a);
            } else {
                sendi[j] = 0; recvi[j] = 0;
                #pragma unroll
                for (int n = 0; n < 5; n++) ef[j][n] = 0.0f;
                cur[j] = zero4;
                stA_tf32(sAu, row, fo, zero4);
            }
        }
        __syncthreads();

        // ---- stage 1: e1 = e + swish(agg @ Wtb + btb)
        gemm_stage(sWtb, sAu, sD, warp, lane);
        __syncthreads();
        {
            float4 b4 = *(const float4*)&sbtb[fo];
            #pragma unroll
            for (int j = 0; j < 4; j++){
                const int row = warp*4 + j;
                float4 d = ldD(sD, row, fo);
                cur[j] = add4(cur[j], swish4(add4(d, b4)));
                stA_tf32(sAu, row, fo, cur[j]);
            }
        }
        __syncthreads();

        // ---- stage 2: e2 = e1 + swish(pi[s]+pj[r]+e1@We1e+be1) * (ef0@We0)
        gemm_stage(sWe1, sAu, sD, warp, lane);
        __syncthreads();
        {
            float4 p0[4];
            #pragma unroll
            for (int j = 0; j < 4; j++) p0[j] = zero4;
            #pragma unroll
            for (int n = 0; n < 5; n++){
                float4 w = *(const float4*)&sWe0[n*FD + fo];
                #pragma unroll
                for (int j = 0; j < 4; j++) fma4(p0[j], ef[j][n], w);
            }
            float4 b4 = *(const float4*)&sbe1[fo];
            #pragma unroll
            for (int j = 0; j < 4; j++){
                const int row = warp*4 + j;
                float4 d = ldD(sD, row, fo);
                float4 a = *(const float4*)&g_pi[(size_t)sendi[j]*FD + fo];
                float4 b = *(const float4*)&g_pj[(size_t)recvi[j]*FD + fo];
                float4 pre = make_float4(d.x+b4.x+a.x+b.x, d.y+b4.y+a.y+b.y,
                                         d.z+b4.z+a.z+b.z, d.w+b4.w+a.w+b.w);
                cur[j] = add4(cur[j], mul4(swish4(pre), p0[j]));
                if (ok[j]) *(float4*)&g_e[(size_t)(base+j)*FD + fo] = cur[j];
                stA_tf32(sAu, row, fo, cur[j]);
            }
        }
        __syncthreads();

        // ---- stage 3: v[recv] += swish(pai[s]+paj[r]+e2@Wa1e+ba1) * (ef0@Wa0)
        gemm_stage(sWa1, sAu, sD, warp, lane);
        __syncthreads();
        {
            float4 p0[4];
            #pragma unroll
            for (int j = 0; j < 4; j++) p0[j] = zero4;
            #pragma unroll
            for (int n = 0; n < 5; n++){
                float4 w = *(const float4*)&sWa0[n*FD + fo];
                #pragma unroll
                for (int j = 0; j < 4; j++) fma4(p0[j], ef[j][n], w);
            }
            float4 b4 = *(const float4*)&sba1[fo];
            #pragma unroll
            for (int j = 0; j < 4; j++){
                if (ok[j]){
                    const int row = warp*4 + j;
                    float4 d = ldD(sD, row, fo);
                    float4 a = *(const float4*)&g_pai[(size_t)sendi[j]*FD + fo];
                    float4 b = *(const float4*)&g_paj[(size_t)recvi[j]*FD + fo];
                    float4 pre = make_float4(d.x+b4.x+a.x+b.x, d.y+b4.y+a.y+b.y,
                                             d.z+b4.z+a.z+b.z, d.w+b4.w+a.w+b.w);
                    float4 m = mul4(swish4(pre), p0[j]);
                    red4(&g_v[(size_t)recvi[j]*FD + fo], m);
                }
            }
        }
        __syncthreads();
    }
}

// ------------------- final readout MLP -------------------------------------
__global__ __launch_bounds__(128)
void k_final(const float* __restrict__ W1, const float* __restrict__ b1,
             const float* __restrict__ W2, const float* __restrict__ b2,
             const float* __restrict__ W3, const float* __restrict__ b3,
             float* __restrict__ out, int N)
{
    __shared__ float sv[FD];
    __shared__ float sh[FD];
    __shared__ float sred[4];
    int n = blockIdx.x;
    if (n >= N) return;
    int t = threadIdx.x;
    sv[t] = g_v[(size_t)n*FD + t];
    __syncthreads();
    float acc = b1[t];
    #pragma unroll 8
    for (int k = 0; k < FD; k++) acc = fmaf(sv[k], W1[k*FD + t], acc);
    sh[t] = swishf(acc);
    __syncthreads();
    acc = b2[t];
    #pragma unroll 8
    for (int k = 0; k < FD; k++) acc = fmaf(sh[k], W2[k*FD + t], acc);
    float prod = swishf(acc) * W3[t];
    #pragma unroll
    for (int o = 16; o > 0; o >>= 1) prod += __shfl_down_sync(0xffffffffu, prod, o);
    if ((t & 31) == 0) sred[t >> 5] = prod;
    __syncthreads();
    if (t == 0) out[n] = sred[0] + sred[1] + sred[2] + sred[3] + b3[0];
}

// ------------------------- launch ------------------------------------------
extern "C" void kernel_launch(void* const* d_in, const int* in_sizes, int n_in,
                              void* d_out, int out_size)
{
    const int*   atomic_numbers = (const int*  )d_in[0];
    const int*   edge_index     = (const int*  )d_in[1];
    const float* edge_dist      = (const float*)d_in[2];
    const int*   tbi            = (const int*  )d_in[3];
    const float* norm_ik        = (const float*)d_in[4];
    const float* cos_ang        = (const float*)d_in[5];
    const int*   tnb            = (const int*  )d_in[6];
    const int*   tna            = (const int*  )d_in[7];
    const float* emb            = (const float*)d_in[8];
    const float* W_enc          = (const float*)d_in[9];
    const float* b_enc          = (const float*)d_in[10];
    const float* W_angle        = (const float*)d_in[11];
    const float* Wg             = (const float*)d_in[12];
    const float* bg             = (const float*)d_in[13];
    const float* W_tb           = (const float*)d_in[14];
    const float* b_tb           = (const float*)d_in[15];
    const float* We1            = (const float*)d_in[16];
    const float* be1            = (const float*)d_in[17];
    const float* We0            = (const float*)d_in[18];
    const float* Wa1            = (const float*)d_in[19];
    const float* ba1            = (const float*)d_in[20];
    const float* Wa0            = (const float*)d_in[21];
    const float* W1             = (const float*)d_in[22];
    const float* b1             = (const float*)d_in[23];
    const float* W2             = (const float*)d_in[24];
    const float* b2             = (const float*)d_in[25];
    const float* W3             = (const float*)d_in[26];
    const float* b3             = (const float*)d_in[27];

    const int N = in_sizes[0];
    const int E = in_sizes[2];
    const int A = in_sizes[4];
    const int G = in_sizes[6];
    float* out = (float*)d_out;

    cudaFuncSetAttribute(k_edge_fused, cudaFuncAttributeMaxDynamicSharedMemorySize,
                         SMEM_EDGE_BYTES);

    float* aggp = nullptr;
    cudaGetSymbolAddress((void**)&aggp, g_agg);

    k_offsets  <<<1, 32>>>(tnb, tna, G);
    k_angle_pre<<<(A + 255) / 256, 256>>>(tbi, norm_ik, cos_ang, edge_index, A, E, G);
    k_edge_init<<<(E + 3) / 4, 128>>>(edge_dist, W_enc, b_enc, E);
    k_vinit    <<<(N * 32 + 255) / 256, 256>>>(atomic_numbers, emb, N);

    for (int b = 0; b < 4; b++){
        cudaMemsetAsync(aggp, 0, (size_t)E * FD * sizeof(float), 0);
        k_gate_pre<<<(N + 7) / 8, 256>>>(Wg + (size_t)b*FD*FD, bg + (size_t)b*FD,
                                         We1 + (size_t)b*3*FD*FD, Wa1 + (size_t)b*3*FD*FD, N);
        k_angle<<<1184, 256>>>(W_angle + (size_t)b*16*FD, A);
        k_edge_fused<<<152, 128, SMEM_EDGE_BYTES>>>(
            W_tb + (size_t)b*FD*FD,            b_tb + (size_t)b*FD,
            We1  + (size_t)b*3*FD*FD + 2*FD*FD, be1 + (size_t)b*FD,
            We0  + (size_t)b*5*FD,
            Wa1  + (size_t)b*3*FD*FD + 2*FD*FD, ba1 + (size_t)b*FD,
            Wa0  + (size_t)b*5*FD,
            edge_index, E);
    }

    k_final<<<N, 128>>>(W1, b1, W2, b2, W3, b3, out, N);
}

// round 13
// speedup vs baseline: 1.6335x; 1.3457x over previous
#include <cuda_runtime.h>
#include <math.h>
#include <stdint.h>

#define FD   128
#define EMAX 200000
#define NMAX 8000
#define AMAX 400000
#define GMAX 128
#define PI_F 3.14159265358979323846f

// ------------------------- scratch (device globals; no allocs) -------------
__device__ float g_e   [(size_t)EMAX * FD];
__device__ float g_agg [(size_t)EMAX * FD];
__device__ float g_ef0 [(size_t)EMAX * 5];
__device__ float g_v   [(size_t)NMAX * FD];
__device__ float g_gate[(size_t)NMAX * FD];
__device__ float g_pi  [(size_t)NMAX * FD];
__device__ float g_pj  [(size_t)NMAX * FD];
__device__ float g_pai [(size_t)NMAX * FD];
__device__ float g_paj [(size_t)NMAX * FD];
__device__ float g_angf[(size_t)AMAX * 16];
__device__ int   g_iij [AMAX];
__device__ int   g_kat [AMAX];
__device__ int   g_boff[GMAX];
__device__ int   g_acum[GMAX + 1];

// ------------------------- helpers ----------------------------------------
__device__ __forceinline__ void fma4(float4& a, float s, float4 b){
    a.x = fmaf(s, b.x, a.x);
    a.y = fmaf(s, b.y, a.y);
    a.z = fmaf(s, b.z, a.z);
    a.w = fmaf(s, b.w, a.w);
}
__device__ __forceinline__ float sigmf(float x){ return __fdividef(1.0f, 1.0f + __expf(-x)); }
__device__ __forceinline__ float swishf(float x){ return x * sigmf(x); }
__device__ __forceinline__ float4 swish4(float4 a){
    return make_float4(swishf(a.x), swishf(a.y), swishf(a.z), swishf(a.w));
}
__device__ __forceinline__ float4 sigm4(float4 a){
    return make_float4(sigmf(a.x), sigmf(a.y), sigmf(a.z), sigmf(a.w));
}
__device__ __forceinline__ float4 add4(float4 a, float4 b){
    return make_float4(a.x+b.x, a.y+b.y, a.z+b.z, a.w+b.w);
}
__device__ __forceinline__ float4 mul4(float4 a, float4 b){
    return make_float4(a.x*b.x, a.y*b.y, a.z*b.z, a.w*b.w);
}
__device__ __forceinline__ void red4(float* p, float4 v){
    asm volatile("red.global.add.v4.f32 [%0], {%1,%2,%3,%4};"
                 :: "l"(p), "f"(v.x), "f"(v.y), "f"(v.z), "f"(v.w) : "memory");
}
__device__ __forceinline__ uint32_t f2tf(float x){
    uint32_t u; asm("cvt.rna.tf32.f32 %0, %1;" : "=r"(u) : "f"(x)); return u;
}
__device__ __forceinline__ void mma_tf32(float c[4],
    uint32_t a0, uint32_t a1, uint32_t a2, uint32_t a3,
    uint32_t b0, uint32_t b1)
{
    asm volatile(
        "mma.sync.aligned.m16n8k8.row.col.f32.tf32.tf32.f32 "
        "{%0,%1,%2,%3}, {%4,%5,%6,%7}, {%8,%9}, {%0,%1,%2,%3};"
        : "+f"(c[0]), "+f"(c[1]), "+f"(c[2]), "+f"(c[3])
        : "r"(a0), "r"(a1), "r"(a2), "r"(a3), "r"(b0), "r"(b1));
}

// ------------------------- prep kernels ------------------------------------
__global__ void k_offsets(const int* __restrict__ tnb, const int* __restrict__ tna, int G){
    if (threadIdx.x == 0 && blockIdx.x == 0){
        int ob = 0, oa = 0;
        g_acum[0] = 0;
        for (int g = 0; g < G; g++){
            g_boff[g] = ob;
            ob += tnb[g];
            oa += tna[g];
            g_acum[g + 1] = oa;
        }
    }
}

__global__ void k_angle_pre(const int* __restrict__ tbi,
                            const float* __restrict__ norm_ik,
                            const float* __restrict__ cosang,
                            const int* __restrict__ edge_index,
                            int A, int E, int G)
{
    int a = blockIdx.x * blockDim.x + threadIdx.x;
    if (a >= A) return;
    int lo = 0, hi = G - 1;
    while (lo < hi){ int mid = (lo + hi + 1) >> 1; if (g_acum[mid] <= a) lo = mid; else hi = mid - 1; }
    int off = g_boff[lo];
    int iij = tbi[2*a]     + off;
    int iik = tbi[2*a + 1] + off;
    g_iij[a] = iij;
    g_kat[a] = edge_index[E + iik];

    float r = norm_ik[a];
    float c = cosang[a];
    float x = r * 0.25f;
    float x2 = x*x, x3 = x2*x;
    float fc = 1.0f - 6.0f*x3*x2 + 15.0f*x2*x2 - 10.0f*x3;
    float invr = 1.0f / r;
    float s2 = fc * fc * invr;
    float rad[4];
    #pragma unroll
    for (int n = 0; n < 4; n++) rad[n] = sinf((float)(n+1) * PI_F * x) * s2;
    float P0 = 1.0f, P1 = c;
    float P2 = 0.5f * (3.0f*c*c - 1.0f);
    float P3 = 0.5f * c * (5.0f*c*c - 3.0f);
    #pragma unroll
    for (int n = 0; n < 4; n++)
        *(float4*)&g_angf[(size_t)a*16 + n*4] = make_float4(rad[n]*P0, rad[n]*P1, rad[n]*P2, rad[n]*P3);
}

__global__ void k_edge_init(const float* __restrict__ edge_dist,
                            const float* __restrict__ W_enc,
                            const float* __restrict__ b_enc, int E)
{
    int gw   = (blockIdx.x * blockDim.x + threadIdx.x) >> 5;
    int lane = threadIdx.x & 31;
    if (gw >= E) return;
    float r    = edge_dist[gw];
    float invr = 1.0f / r;
    const float C = sqrtf(2.0f / 5.0f);
    float ef[5];
    #pragma unroll
    for (int n = 0; n < 5; n++) ef[n] = C * sinf((float)(n+1) * PI_F * r * 0.2f) * invr;
    if (lane < 5) g_ef0[(size_t)gw*5 + lane] = ef[lane];
    int fo = lane * 4;
    float4 acc = *(const float4*)&b_enc[fo];
    #pragma unroll
    for (int n = 0; n < 5; n++){
        float4 w = *(const float4*)&W_enc[n*FD + fo];
        fma4(acc, ef[n], w);
    }
    *(float4*)&g_e[(size_t)gw*FD + fo] = swish4(acc);
}

__global__ void k_vinit(const int* __restrict__ z, const float* __restrict__ emb, int N){
    int t = blockIdx.x * blockDim.x + threadIdx.x;
    if (t >= N * 32) return;
    int n = t >> 5, fo = (t & 31) * 4;
    *(float4*)&g_v[(size_t)n*FD + fo] = *(const float4*)&emb[(size_t)z[n]*FD + fo];
}

// ------------------- per-block: atom precompute (gate + concat parts) -------
__global__ __launch_bounds__(256)
void k_gate_pre(const float* __restrict__ Wg,  const float* __restrict__ bg,
                const float* __restrict__ We1b, const float* __restrict__ Wa1b, int N)
{
    __shared__ float sv[8][FD];
    const int warp = threadIdx.x >> 5, lane = threadIdx.x & 31;
    const int fo = lane * 4;
    for (int base = blockIdx.x * 8; base < N; base += gridDim.x * 8){
        int na = N - base; if (na > 8) na = 8;
        __syncthreads();
        for (int idx = threadIdx.x; idx < na * 32; idx += blockDim.x){
            int rr = idx >> 5, cc = (idx & 31) * 4;
            *(float4*)&sv[rr][cc] = *(const float4*)&g_v[(size_t)(base+rr)*FD + cc];
        }
        __syncthreads();
        if (warp < 5){
            const float* W = (warp == 0) ? Wg
                           : (warp == 1) ? We1b
                           : (warp == 2) ? (We1b + FD*FD)
                           : (warp == 3) ? Wa1b
                           :               (Wa1b + FD*FD);
            float4 acc[8];
            #pragma unroll
            for (int j = 0; j < 8; j++) acc[j] = make_float4(0,0,0,0);
            #pragma unroll 4
            for (int k4 = 0; k4 < 32; k4++){
                float4 w0 = *(const float4*)&W[(k4*4+0)*FD + fo];
                float4 w1 = *(const float4*)&W[(k4*4+1)*FD + fo];
                float4 w2 = *(const float4*)&W[(k4*4+2)*FD + fo];
                float4 w3 = *(const float4*)&W[(k4*4+3)*FD + fo];
                #pragma unroll
                for (int j = 0; j < 8; j++){
                    float4 s = *(const float4*)&sv[j][k4*4];
                    fma4(acc[j], s.x, w0); fma4(acc[j], s.y, w1);
                    fma4(acc[j], s.z, w2); fma4(acc[j], s.w, w3);
                }
            }
            if (warp == 0){
                float4 b4 = *(const float4*)&bg[fo];
                for (int j = 0; j < na; j++)
                    *(float4*)&g_gate[(size_t)(base+j)*FD + fo] = sigm4(add4(acc[j], b4));
            } else {
                float* dst = (warp == 1) ? g_pi : (warp == 2) ? g_pj : (warp == 3) ? g_pai : g_paj;
                for (int j = 0; j < na; j++)
                    *(float4*)&dst[(size_t)(base+j)*FD + fo] = acc[j];
            }
        }
    }
}

// ------------------- per-block: angle message scatter (R9 version) ----------
__global__ __launch_bounds__(256)
void k_angle(const float* __restrict__ Wang, int A)
{
    __shared__ float sW[16 * FD];
    for (int i = threadIdx.x; i < 16*FD/4; i += blockDim.x)
        ((float4*)sW)[i] = ((const float4*)Wang)[i];
    __syncthreads();
    const int lane = threadIdx.x & 31;
    const int fo = lane * 4;
    int gw = (blockIdx.x * blockDim.x + threadIdx.x) >> 5;
    int nw = (gridDim.x * blockDim.x) >> 5;
    for (int a = gw; a < A; a += nw){
        int iij = g_iij[a], kat = g_kat[a];
        const float4* af = (const float4*)&g_angf[(size_t)a*16];
        float4 acc = make_float4(0,0,0,0);
        #pragma unroll
        for (int k4 = 0; k4 < 4; k4++){
            float4 s  = af[k4];
            float4 w0 = *(const float4*)&sW[(k4*4+0)*FD + fo];
            float4 w1 = *(const float4*)&sW[(k4*4+1)*FD + fo];
            float4 w2 = *(const float4*)&sW[(k4*4+2)*FD + fo];
            float4 w3 = *(const float4*)&sW[(k4*4+3)*FD + fo];
            fma4(acc, s.x, w0); fma4(acc, s.y, w1); fma4(acc, s.z, w2); fma4(acc, s.w, w3);
        }
        float4 g = *(const float4*)&g_gate[(size_t)kat*FD + fo];
        red4(&g_agg[(size_t)iij*FD + fo], mul4(acc, g));
    }
}

// ------------------- per-block: fused edge update, tf32 MMA, 8 warps --------
// 256 threads, TILE_E=32 edges per CTA iteration.
// A tile and D tile SHARE one 32x128 smem buffer (barrier-separated phases).
#define TILE_E 32
#define SMEM_EDGE_BYTES ((3*16384 + 32*128 + 2*5*FD + 3*FD) * 4)

// compute phase: c = A[32x128] @ W[128x128] fragment-owned
__device__ __forceinline__ void gemm_compute(const uint32_t* __restrict__ sW,
                                             const uint32_t* __restrict__ sA,
                                             int warp, int lane, float c[4][4])
{
    const int rt  = warp >> 2;          // row-tile 0..1 (m16)
    const int cw  = warp & 3;           // coltile group: n8 tiles cw*4+i
    const int gid = lane >> 2;          // 0..7
    const int t   = lane & 3;           // 0..3
    const int r0  = rt*16 + gid, r1 = r0 + 8;
    const int sz  = (gid & 3) * 8;      // (r&3)==gid&3 for both rows
    #pragma unroll
    for (int i = 0; i < 4; i++){ c[i][0]=0.f; c[i][1]=0.f; c[i][2]=0.f; c[i][3]=0.f; }
    #pragma unroll
    for (int ks = 0; ks < 16; ks++){
        const int k0 = ks*8 + t;
        uint32_t a0 = sA[r0*128 + ((k0    ) ^ sz)];
        uint32_t a1 = sA[r1*128 + ((k0    ) ^ sz)];
        uint32_t a2 = sA[r0*128 + ((k0 + 4) ^ sz)];
        uint32_t a3 = sA[r1*128 + ((k0 + 4) ^ sz)];
        #pragma unroll
        for (int i = 0; i < 4; i++){
            const int col = (cw*4 + i)*8 + gid;
            uint32_t b0 = sW[(k0    )*128 + (col ^ (t*8))];
            uint32_t b1 = sW[(k0 + 4)*128 + (col ^ (t*8))];
            mma_tf32(c[i], a0, a1, a2, a3, b0, b1);
        }
    }
}

__device__ __forceinline__ void gemm_store(float* __restrict__ sD,
                                           int warp, int lane, const float c[4][4])
{
    const int rt  = warp >> 2;
    const int cw  = warp & 3;
    const int gid = lane >> 2;
    const int t   = lane & 3;
    const int r0  = rt*16 + gid, r1 = r0 + 8;
    const int sz  = (gid & 3) * 8;
    #pragma unroll
    for (int i = 0; i < 4; i++){
        const int colb = (cw*4 + i)*8 + 2*t;
        *(float2*)&sD[r0*128 + (colb ^ sz)] = make_float2(c[i][0], c[i][1]);
        *(float2*)&sD[r1*128 + (colb ^ sz)] = make_float2(c[i][2], c[i][3]);
    }
}

__device__ __forceinline__ void stA_tf32(uint32_t* __restrict__ sA, int row, int fo, float4 v){
    uint4 u = make_uint4(f2tf(v.x), f2tf(v.y), f2tf(v.z), f2tf(v.w));
    *(uint4*)&sA[row*128 + (fo ^ ((row & 3)*8))] = u;
}
__device__ __forceinline__ float4 ldD(const float* __restrict__ sD, int row, int fo){
    return *(const float4*)&sD[row*128 + (fo ^ ((row & 3)*8))];
}

__global__ __launch_bounds__(256, 1)
void k_edge_fused(const float* __restrict__ Wtb,  const float* __restrict__ btb,
                  const float* __restrict__ We1e, const float* __restrict__ be1,
                  const float* __restrict__ We0,
                  const float* __restrict__ Wa1e, const float* __restrict__ ba1,
                  const float* __restrict__ Wa0,
                  const int* __restrict__ edge_index, int E)
{
    extern __shared__ char smraw[];
    uint32_t* sWtb = (uint32_t*)smraw;
    uint32_t* sWe1 = sWtb + 16384;
    uint32_t* sWa1 = sWe1 + 16384;
    uint32_t* sAD  = sWa1 + 16384;           // 32 x 128: A (tf32) then D (fp32)
    float*    sADf = (float*)sAD;
    float*    sWe0 = (float*)(sAD + 32*128);
    float*    sWa0 = sWe0 + 5*FD;
    float*    sbtb = sWa0 + 5*FD;
    float*    sbe1 = sbtb + FD;
    float*    sba1 = sbe1 + FD;

    for (int i = threadIdx.x; i < FD*FD; i += blockDim.x){
        int k = i >> 7, col = i & 127;
        int dst = k*128 + (col ^ ((k & 3)*8));
        sWtb[dst] = f2tf(Wtb [i]);
        sWe1[dst] = f2tf(We1e[i]);
        sWa1[dst] = f2tf(Wa1e[i]);
    }
    for (int i = threadIdx.x; i < 5*FD; i += blockDim.x){
        sWe0[i] = We0[i];
        sWa0[i] = Wa0[i];
    }
    if (threadIdx.x < FD){
        sbtb[threadIdx.x] = btb[threadIdx.x];
        sbe1[threadIdx.x] = be1[threadIdx.x];
        sba1[threadIdx.x] = ba1[threadIdx.x];
    }
    __syncthreads();

    const int warp = threadIdx.x >> 5;
    const int lane = threadIdx.x & 31;
    const int fo = lane * 4;
    const float4 zero4 = make_float4(0,0,0,0);
    float c[4][4];

    for (int base0 = blockIdx.x * TILE_E; base0 < E; base0 += gridDim.x * TILE_E){
        const int base = base0 + warp * 4;   // warp owns rows warp*4..warp*4+3

        int sendi[4], recvi[4];
        bool ok[4];
        float ef[4][5];
        float4 cur[4];
        #pragma unroll
        for (int j = 0; j < 4; j++){
            const int row = warp*4 + j;
            const int eid = base + j;
            ok[j] = (eid < E);
            if (ok[j]){
                sendi[j] = edge_index[eid];
                recvi[j] = edge_index[E + eid];
                #pragma unroll
                for (int n = 0; n < 5; n++) ef[j][n] = g_ef0[(size_t)eid*5 + n];
                float4 a = *(const float4*)&g_agg[(size_t)eid*FD + fo];
                cur[j] = *(const float4*)&g_e[(size_t)eid*FD + fo];
                stA_tf32(sAD, row, fo, a);
            } else {
                sendi[j] = 0; recvi[j] = 0;
                #pragma unroll
                for (int n = 0; n < 5; n++) ef[j][n] = 0.0f;
                cur[j] = zero4;
                stA_tf32(sAD, row, fo, zero4);
            }
        }
        __syncthreads();

        // ---- stage 1: e1 = e + swish(agg @ Wtb + btb)
        gemm_compute(sWtb, sAD, warp, lane, c);
        __syncthreads();
        gemm_store(sADf, warp, lane, c);
        __syncthreads();
        {
            float4 b4 = *(const float4*)&sbtb[fo];
            #pragma unroll
            for (int j = 0; j < 4; j++){
                const int row = warp*4 + j;
                float4 d = ldD(sADf, row, fo);
                cur[j] = add4(cur[j], swish4(add4(d, b4)));
                stA_tf32(sAD, row, fo, cur[j]);
            }
        }
        __syncthreads();

        // ---- stage 2: e2 = e1 + swish(pi[s]+pj[r]+e1@We1e+be1) * (ef0@We0)
        gemm_compute(sWe1, sAD, warp, lane, c);
        __syncthreads();
        gemm_store(sADf, warp, lane, c);
        __syncthreads();
        {
            float4 p0[4];
            #pragma unroll
            for (int j = 0; j < 4; j++) p0[j] = zero4;
            #pragma unroll
            for (int n = 0; n < 5; n++){
                float4 w = *(const float4*)&sWe0[n*FD + fo];
                #pragma unroll
                for (int j = 0; j < 4; j++) fma4(p0[j], ef[j][n], w);
            }
            float4 b4 = *(const float4*)&sbe1[fo];
            #pragma unroll
            for (int j = 0; j < 4; j++){
                const int row = warp*4 + j;
                float4 d = ldD(sADf, row, fo);
                float4 a = *(const float4*)&g_pi[(size_t)sendi[j]*FD + fo];
                float4 b = *(const float4*)&g_pj[(size_t)recvi[j]*FD + fo];
                float4 pre = make_float4(d.x+b4.x+a.x+b.x, d.y+b4.y+a.y+b.y,
                                         d.z+b4.z+a.z+b.z, d.w+b4.w+a.w+b.w);
                cur[j] = add4(cur[j], mul4(swish4(pre), p0[j]));
                if (ok[j]) *(float4*)&g_e[(size_t)(base+j)*FD + fo] = cur[j];
            }
        }
        __syncthreads();           // all D reads done before overwriting with A
        #pragma unroll
        for (int j = 0; j < 4; j++) stA_tf32(sAD, warp*4 + j, fo, cur[j]);
        __syncthreads();

        // ---- stage 3: v[recv] += swish(pai[s]+paj[r]+e2@Wa1e+ba1) * (ef0@Wa0)
        gemm_compute(sWa1, sAD, warp, lane, c);
        __syncthreads();
        gemm_store(sADf, warp, lane, c);
        __syncthreads();
        {
            float4 p0[4];
            #pragma unroll
            for (int j = 0; j < 4; j++) p0[j] = zero4;
            #pragma unroll
            for (int n = 0; n < 5; n++){
                float4 w = *(const float4*)&sWa0[n*FD + fo];
                #pragma unroll
                for (int j = 0; j < 4; j++) fma4(p0[j], ef[j][n], w);
            }
            float4 b4 = *(const float4*)&sba1[fo];
            #pragma unroll
            for (int j = 0; j < 4; j++){
                if (ok[j]){
                    const int row = warp*4 + j;
                    float4 d = ldD(sADf, row, fo);
                    float4 a = *(const float4*)&g_pai[(size_t)sendi[j]*FD + fo];
                    float4 b = *(const float4*)&g_paj[(size_t)recvi[j]*FD + fo];
                    float4 pre = make_float4(d.x+b4.x+a.x+b.x, d.y+b4.y+a.y+b.y,
                                             d.z+b4.z+a.z+b.z, d.w+b4.w+a.w+b.w);
                    float4 m = mul4(swish4(pre), p0[j]);
                    red4(&g_v[(size_t)recvi[j]*FD + fo], m);
                }
            }
        }
        __syncthreads();
    }
}

// ------------------- final readout MLP -------------------------------------
__global__ __launch_bounds__(128)
void k_final(const float* __restrict__ W1, const float* __restrict__ b1,
             const float* __restrict__ W2, const float* __restrict__ b2,
             const float* __restrict__ W3, const float* __restrict__ b3,
             float* __restrict__ out, int N)
{
    __shared__ float sv[FD];
    __shared__ float sh[FD];
    __shared__ float sred[4];
    int n = blockIdx.x;
    if (n >= N) return;
    int t = threadIdx.x;
    sv[t] = g_v[(size_t)n*FD + t];
    __syncthreads();
    float acc = b1[t];
    #pragma unroll 8
    for (int k = 0; k < FD; k++) acc = fmaf(sv[k], W1[k*FD + t], acc);
    sh[t] = swishf(acc);
    __syncthreads();
    acc = b2[t];
    #pragma unroll 8
    for (int k = 0; k < FD; k++) acc = fmaf(sh[k], W2[k*FD + t], acc);
    float prod = swishf(acc) * W3[t];
    #pragma unroll
    for (int o = 16; o > 0; o >>= 1) prod += __shfl_down_sync(0xffffffffu, prod, o);
    if ((t & 31) == 0) sred[t >> 5] = prod;
    __syncthreads();
    if (t == 0) out[n] = sred[0] + sred[1] + sred[2] + sred[3] + b3[0];
}

// ------------------------- launch ------------------------------------------
extern "C" void kernel_launch(void* const* d_in, const int* in_sizes, int n_in,
                              void* d_out, int out_size)
{
    const int*   atomic_numbers = (const int*  )d_in[0];
    const int*   edge_index     = (const int*  )d_in[1];
    const float* edge_dist      = (const float*)d_in[2];
    const int*   tbi            = (const int*  )d_in[3];
    const float* norm_ik        = (const float*)d_in[4];
    const float* cos_ang        = (const float*)d_in[5];
    const int*   tnb            = (const int*  )d_in[6];
    const int*   tna            = (const int*  )d_in[7];
    const float* emb            = (const float*)d_in[8];
    const float* W_enc          = (const float*)d_in[9];
    const float* b_enc          = (const float*)d_in[10];
    const float* W_angle        = (const float*)d_in[11];
    const float* Wg             = (const float*)d_in[12];
    const float* bg             = (const float*)d_in[13];
    const float* W_tb           = (const float*)d_in[14];
    const float* b_tb           = (const float*)d_in[15];
    const float* We1            = (const float*)d_in[16];
    const float* be1            = (const float*)d_in[17];
    const float* We0            = (const float*)d_in[18];
    const float* Wa1            = (const float*)d_in[19];
    const float* ba1            = (const float*)d_in[20];
    const float* Wa0            = (const float*)d_in[21];
    const float* W1             = (const float*)d_in[22];
    const float* b1             = (const float*)d_in[23];
    const float* W2             = (const float*)d_in[24];
    const float* b2             = (const float*)d_in[25];
    const float* W3             = (const float*)d_in[26];
    const float* b3             = (const float*)d_in[27];

    const int N = in_sizes[0];
    const int E = in_sizes[2];
    const int A = in_sizes[4];
    const int G = in_sizes[6];
    float* out = (float*)d_out;

    cudaFuncSetAttribute(k_edge_fused, cudaFuncAttributeMaxDynamicSharedMemorySize,
                         SMEM_EDGE_BYTES);

    float* aggp = nullptr;
    cudaGetSymbolAddress((void**)&aggp, g_agg);

    k_offsets  <<<1, 32>>>(tnb, tna, G);
    k_angle_pre<<<(A + 255) / 256, 256>>>(tbi, norm_ik, cos_ang, edge_index, A, E, G);
    k_edge_init<<<(E + 3) / 4, 128>>>(edge_dist, W_enc, b_enc, E);
    k_vinit    <<<(N * 32 + 255) / 256, 256>>>(atomic_numbers, emb, N);

    for (int b = 0; b < 4; b++){
        cudaMemsetAsync(aggp, 0, (size_t)E * FD * sizeof(float), 0);
        k_gate_pre<<<(N + 7) / 8, 256>>>(Wg + (size_t)b*FD*FD, bg + (size_t)b*FD,
                                         We1 + (size_t)b*3*FD*FD, Wa1 + (size_t)b*3*FD*FD, N);
        k_angle<<<1184, 256>>>(W_angle + (size_t)b*16*FD, A);
        k_edge_fused<<<152, 256, SMEM_EDGE_BYTES>>>(
            W_tb + (size_t)b*FD*FD,            b_tb + (size_t)b*FD,
            We1  + (size_t)b*3*FD*FD + 2*FD*FD, be1 + (size_t)b*FD,
            We0  + (size_t)b*5*FD,
            Wa1  + (size_t)b*3*FD*FD + 2*FD*FD, ba1 + (size_t)b*FD,
            Wa0  + (size_t)b*5*FD,
            edge_index, E);
    }

    k_final<<<N, 128>>>(W1, b1, W2, b2, W3, b3, out, N);
}

// round 14
// speedup vs baseline: 1.7621x; 1.0787x over previous
#include <cuda_runtime.h>
#include <math.h>
#include <stdint.h>

#define FD   128
#define EMAX 200000
#define NMAX 8000
#define AMAX 400000
#define GMAX 128
#define PI_F 3.14159265358979323846f

// ------------------------- scratch (device globals; no allocs) -------------
__device__ float g_e   [(size_t)EMAX * FD];
__device__ float g_agg [(size_t)EMAX * FD];
__device__ float g_ef0 [(size_t)EMAX * 5];
__device__ float g_v   [(size_t)NMAX * FD];
__device__ float g_gate[(size_t)NMAX * FD];
__device__ float g_pi  [(size_t)NMAX * FD];
__device__ float g_pj  [(size_t)NMAX * FD];
__device__ float g_pai [(size_t)NMAX * FD];
__device__ float g_paj [(size_t)NMAX * FD];
__device__ float g_angf[(size_t)AMAX * 16];
__device__ int   g_iij [AMAX];
__device__ int   g_kat [AMAX];
__device__ int   g_boff[GMAX];
__device__ int   g_acum[GMAX + 1];

// ------------------------- helpers ----------------------------------------
__device__ __forceinline__ void fma4(float4& a, float s, float4 b){
    a.x = fmaf(s, b.x, a.x);
    a.y = fmaf(s, b.y, a.y);
    a.z = fmaf(s, b.z, a.z);
    a.w = fmaf(s, b.w, a.w);
}
__device__ __forceinline__ float sigmf(float x){ return __fdividef(1.0f, 1.0f + __expf(-x)); }
__device__ __forceinline__ float swishf(float x){ return x * sigmf(x); }
__device__ __forceinline__ float4 swish4(float4 a){
    return make_float4(swishf(a.x), swishf(a.y), swishf(a.z), swishf(a.w));
}
__device__ __forceinline__ float4 sigm4(float4 a){
    return make_float4(sigmf(a.x), sigmf(a.y), sigmf(a.z), sigmf(a.w));
}
__device__ __forceinline__ float4 add4(float4 a, float4 b){
    return make_float4(a.x+b.x, a.y+b.y, a.z+b.z, a.w+b.w);
}
__device__ __forceinline__ float4 mul4(float4 a, float4 b){
    return make_float4(a.x*b.x, a.y*b.y, a.z*b.z, a.w*b.w);
}
__device__ __forceinline__ void red4(float* p, float4 v){
    asm volatile("red.global.add.v4.f32 [%0], {%1,%2,%3,%4};"
                 :: "l"(p), "f"(v.x), "f"(v.y), "f"(v.z), "f"(v.w) : "memory");
}
__device__ __forceinline__ uint32_t f2tf(float x){
    uint32_t u; asm("cvt.rna.tf32.f32 %0, %1;" : "=r"(u) : "f"(x)); return u;
}
__device__ __forceinline__ void mma_tf32(float c[4],
    uint32_t a0, uint32_t a1, uint32_t a2, uint32_t a3,
    uint32_t b0, uint32_t b1)
{
    asm volatile(
        "mma.sync.aligned.m16n8k8.row.col.f32.tf32.tf32.f32 "
        "{%0,%1,%2,%3}, {%4,%5,%6,%7}, {%8,%9}, {%0,%1,%2,%3};"
        : "+f"(c[0]), "+f"(c[1]), "+f"(c[2]), "+f"(c[3])
        : "r"(a0), "r"(a1), "r"(a2), "r"(a3), "r"(b0), "r"(b1));
}

// ------------------------- prep kernels ------------------------------------
__global__ void k_offsets(const int* __restrict__ tnb, const int* __restrict__ tna, int G){
    if (threadIdx.x == 0 && blockIdx.x == 0){
        int ob = 0, oa = 0;
        g_acum[0] = 0;
        for (int g = 0; g < G; g++){
            g_boff[g] = ob;
            ob += tnb[g];
            oa += tna[g];
            g_acum[g + 1] = oa;
        }
    }
}

__global__ void k_angle_pre(const int* __restrict__ tbi,
                            const float* __restrict__ norm_ik,
                            const float* __restrict__ cosang,
                            const int* __restrict__ edge_index,
                            int A, int E, int G)
{
    int a = blockIdx.x * blockDim.x + threadIdx.x;
    if (a >= A) return;
    int lo = 0, hi = G - 1;
    while (lo < hi){ int mid = (lo + hi + 1) >> 1; if (g_acum[mid] <= a) lo = mid; else hi = mid - 1; }
    int off = g_boff[lo];
    int iij = tbi[2*a]     + off;
    int iik = tbi[2*a + 1] + off;
    g_iij[a] = iij;
    g_kat[a] = edge_index[E + iik];

    float r = norm_ik[a];
    float c = cosang[a];
    float x = r * 0.25f;
    float x2 = x*x, x3 = x2*x;
    float fc = 1.0f - 6.0f*x3*x2 + 15.0f*x2*x2 - 10.0f*x3;
    float invr = 1.0f / r;
    float s2 = fc * fc * invr;
    float rad[4];
    #pragma unroll
    for (int n = 0; n < 4; n++) rad[n] = sinf((float)(n+1) * PI_F * x) * s2;
    float P0 = 1.0f, P1 = c;
    float P2 = 0.5f * (3.0f*c*c - 1.0f);
    float P3 = 0.5f * c * (5.0f*c*c - 3.0f);
    #pragma unroll
    for (int n = 0; n < 4; n++)
        *(float4*)&g_angf[(size_t)a*16 + n*4] = make_float4(rad[n]*P0, rad[n]*P1, rad[n]*P2, rad[n]*P3);
}

__global__ void k_edge_init(const float* __restrict__ edge_dist,
                            const float* __restrict__ W_enc,
                            const float* __restrict__ b_enc, int E)
{
    int gw   = (blockIdx.x * blockDim.x + threadIdx.x) >> 5;
    int lane = threadIdx.x & 31;
    if (gw >= E) return;
    float r    = edge_dist[gw];
    float invr = 1.0f / r;
    const float C = sqrtf(2.0f / 5.0f);
    float ef[5];
    #pragma unroll
    for (int n = 0; n < 5; n++) ef[n] = C * sinf((float)(n+1) * PI_F * r * 0.2f) * invr;
    if (lane < 5) g_ef0[(size_t)gw*5 + lane] = ef[lane];
    int fo = lane * 4;
    float4 acc = *(const float4*)&b_enc[fo];
    #pragma unroll
    for (int n = 0; n < 5; n++){
        float4 w = *(const float4*)&W_enc[n*FD + fo];
        fma4(acc, ef[n], w);
    }
    *(float4*)&g_e[(size_t)gw*FD + fo] = swish4(acc);
}

__global__ void k_vinit(const int* __restrict__ z, const float* __restrict__ emb, int N){
    int t = blockIdx.x * blockDim.x + threadIdx.x;
    if (t >= N * 32) return;
    int n = t >> 5, fo = (t & 31) * 4;
    *(float4*)&g_v[(size_t)n*FD + fo] = *(const float4*)&emb[(size_t)z[n]*FD + fo];
}

// ------------------- per-block: atom precompute (gate + concat parts) -------
__global__ __launch_bounds__(256)
void k_gate_pre(const float* __restrict__ Wg,  const float* __restrict__ bg,
                const float* __restrict__ We1b, const float* __restrict__ Wa1b, int N)
{
    __shared__ float sv[8][FD];
    const int warp = threadIdx.x >> 5, lane = threadIdx.x & 31;
    const int fo = lane * 4;
    for (int base = blockIdx.x * 8; base < N; base += gridDim.x * 8){
        int na = N - base; if (na > 8) na = 8;
        __syncthreads();
        for (int idx = threadIdx.x; idx < na * 32; idx += blockDim.x){
            int rr = idx >> 5, cc = (idx & 31) * 4;
            *(float4*)&sv[rr][cc] = *(const float4*)&g_v[(size_t)(base+rr)*FD + cc];
        }
        __syncthreads();
        if (warp < 5){
            const float* W = (warp == 0) ? Wg
                           : (warp == 1) ? We1b
                           : (warp == 2) ? (We1b + FD*FD)
                           : (warp == 3) ? Wa1b
                           :               (Wa1b + FD*FD);
            float4 acc[8];
            #pragma unroll
            for (int j = 0; j < 8; j++) acc[j] = make_float4(0,0,0,0);
            #pragma unroll 4
            for (int k4 = 0; k4 < 32; k4++){
                float4 w0 = *(const float4*)&W[(k4*4+0)*FD + fo];
                float4 w1 = *(const float4*)&W[(k4*4+1)*FD + fo];
                float4 w2 = *(const float4*)&W[(k4*4+2)*FD + fo];
                float4 w3 = *(const float4*)&W[(k4*4+3)*FD + fo];
                #pragma unroll
                for (int j = 0; j < 8; j++){
                    float4 s = *(const float4*)&sv[j][k4*4];
                    fma4(acc[j], s.x, w0); fma4(acc[j], s.y, w1);
                    fma4(acc[j], s.z, w2); fma4(acc[j], s.w, w3);
                }
            }
            if (warp == 0){
                float4 b4 = *(const float4*)&bg[fo];
                for (int j = 0; j < na; j++)
                    *(float4*)&g_gate[(size_t)(base+j)*FD + fo] = sigm4(add4(acc[j], b4));
            } else {
                float* dst = (warp == 1) ? g_pi : (warp == 2) ? g_pj : (warp == 3) ? g_pai : g_paj;
                for (int j = 0; j < na; j++)
                    *(float4*)&dst[(size_t)(base+j)*FD + fo] = acc[j];
            }
        }
    }
}

// ------------------- per-block: angle message scatter (R9 version) ----------
__global__ __launch_bounds__(256)
void k_angle(const float* __restrict__ Wang, int A)
{
    __shared__ float sW[16 * FD];
    for (int i = threadIdx.x; i < 16*FD/4; i += blockDim.x)
        ((float4*)sW)[i] = ((const float4*)Wang)[i];
    __syncthreads();
    const int lane = threadIdx.x & 31;
    const int fo = lane * 4;
    int gw = (blockIdx.x * blockDim.x + threadIdx.x) >> 5;
    int nw = (gridDim.x * blockDim.x) >> 5;
    for (int a = gw; a < A; a += nw){
        int iij = g_iij[a], kat = g_kat[a];
        const float4* af = (const float4*)&g_angf[(size_t)a*16];
        float4 acc = make_float4(0,0,0,0);
        #pragma unroll
        for (int k4 = 0; k4 < 4; k4++){
            float4 s  = af[k4];
            float4 w0 = *(const float4*)&sW[(k4*4+0)*FD + fo];
            float4 w1 = *(const float4*)&sW[(k4*4+1)*FD + fo];
            float4 w2 = *(const float4*)&sW[(k4*4+2)*FD + fo];
            float4 w3 = *(const float4*)&sW[(k4*4+3)*FD + fo];
            fma4(acc, s.x, w0); fma4(acc, s.y, w1); fma4(acc, s.z, w2); fma4(acc, s.w, w3);
        }
        float4 g = *(const float4*)&g_gate[(size_t)kat*FD + fo];
        red4(&g_agg[(size_t)iij*FD + fo], mul4(acc, g));
    }
}

// ------------------- per-block: fused edge update, tf32 MMA, 8 warps --------
// 256 threads, TILE_E=32 edges per CTA iteration. Grid MUST be <= 148 (1 CTA/SM).
// A tile and D tile SHARE one 32x128 smem buffer (barrier-separated phases).
#define TILE_E 32
#define EDGE_GRID 148
#define SMEM_EDGE_BYTES ((3*16384 + 32*128 + 2*5*FD + 3*FD) * 4)

// compute phase: c = A[32x128] @ W[128x128] fragment-owned
__device__ __forceinline__ void gemm_compute(const uint32_t* __restrict__ sW,
                                             const uint32_t* __restrict__ sA,
                                             int warp, int lane, float c[4][4])
{
    const int rt  = warp >> 2;          // row-tile 0..1 (m16)
    const int cw  = warp & 3;           // coltile group: n8 tiles cw*4+i
    const int gid = lane >> 2;          // 0..7
    const int t   = lane & 3;           // 0..3
    const int r0  = rt*16 + gid, r1 = r0 + 8;
    const int sz  = (gid & 3) * 8;
    #pragma unroll
    for (int i = 0; i < 4; i++){ c[i][0]=0.f; c[i][1]=0.f; c[i][2]=0.f; c[i][3]=0.f; }
    #pragma unroll
    for (int ks = 0; ks < 16; ks++){
        const int k0 = ks*8 + t;
        uint32_t a0 = sA[r0*128 + ((k0    ) ^ sz)];
        uint32_t a1 = sA[r1*128 + ((k0    ) ^ sz)];
        uint32_t a2 = sA[r0*128 + ((k0 + 4) ^ sz)];
        uint32_t a3 = sA[r1*128 + ((k0 + 4) ^ sz)];
        #pragma unroll
        for (int i = 0; i < 4; i++){
            const int col = (cw*4 + i)*8 + gid;
            uint32_t b0 = sW[(k0    )*128 + (col ^ (t*8))];
            uint32_t b1 = sW[(k0 + 4)*128 + (col ^ (t*8))];
            mma_tf32(c[i], a0, a1, a2, a3, b0, b1);
        }
    }
}

__device__ __forceinline__ void gemm_store(float* __restrict__ sD,
                                           int warp, int lane, const float c[4][4])
{
    const int rt  = warp >> 2;
    const int cw  = warp & 3;
    const int gid = lane >> 2;
    const int t   = lane & 3;
    const int r0  = rt*16 + gid, r1 = r0 + 8;
    const int sz  = (gid & 3) * 8;
    #pragma unroll
    for (int i = 0; i < 4; i++){
        const int colb = (cw*4 + i)*8 + 2*t;
        *(float2*)&sD[r0*128 + (colb ^ sz)] = make_float2(c[i][0], c[i][1]);
        *(float2*)&sD[r1*128 + (colb ^ sz)] = make_float2(c[i][2], c[i][3]);
    }
}

__device__ __forceinline__ void stA_tf32(uint32_t* __restrict__ sA, int row, int fo, float4 v){
    uint4 u = make_uint4(f2tf(v.x), f2tf(v.y), f2tf(v.z), f2tf(v.w));
    *(uint4*)&sA[row*128 + (fo ^ ((row & 3)*8))] = u;
}
__device__ __forceinline__ float4 ldD(const float* __restrict__ sD, int row, int fo){
    return *(const float4*)&sD[row*128 + (fo ^ ((row & 3)*8))];
}

__global__ __launch_bounds__(256, 1)
void k_edge_fused(const float* __restrict__ Wtb,  const float* __restrict__ btb,
                  const float* __restrict__ We1e, const float* __restrict__ be1,
                  const float* __restrict__ We0,
                  const float* __restrict__ Wa1e, const float* __restrict__ ba1,
                  const float* __restrict__ Wa0,
                  const int* __restrict__ edge_index, int E)
{
    extern __shared__ char smraw[];
    uint32_t* sWtb = (uint32_t*)smraw;
    uint32_t* sWe1 = sWtb + 16384;
    uint32_t* sWa1 = sWe1 + 16384;
    uint32_t* sAD  = sWa1 + 16384;           // 32 x 128: A (tf32) then D (fp32)
    float*    sADf = (float*)sAD;
    float*    sWe0 = (float*)(sAD + 32*128);
    float*    sWa0 = sWe0 + 5*FD;
    float*    sbtb = sWa0 + 5*FD;
    float*    sbe1 = sbtb + FD;
    float*    sba1 = sbe1 + FD;

    for (int i = threadIdx.x; i < FD*FD; i += blockDim.x){
        int k = i >> 7, col = i & 127;
        int dst = k*128 + (col ^ ((k & 3)*8));
        sWtb[dst] = f2tf(Wtb [i]);
        sWe1[dst] = f2tf(We1e[i]);
        sWa1[dst] = f2tf(Wa1e[i]);
    }
    for (int i = threadIdx.x; i < 5*FD; i += blockDim.x){
        sWe0[i] = We0[i];
        sWa0[i] = Wa0[i];
    }
    if (threadIdx.x < FD){
        sbtb[threadIdx.x] = btb[threadIdx.x];
        sbe1[threadIdx.x] = be1[threadIdx.x];
        sba1[threadIdx.x] = ba1[threadIdx.x];
    }
    __syncthreads();

    const int warp = threadIdx.x >> 5;
    const int lane = threadIdx.x & 31;
    const int fo = lane * 4;
    const float4 zero4 = make_float4(0,0,0,0);
    float c[4][4];

    for (int base0 = blockIdx.x * TILE_E; base0 < E; base0 += gridDim.x * TILE_E){
        const int base = base0 + warp * 4;   // warp owns rows warp*4..warp*4+3

        int sendi[4], recvi[4];
        bool ok[4];
        float ef[4][5];
        float4 cur[4];
        float4 pi_pre[4], pj_pre[4];
        #pragma unroll
        for (int j = 0; j < 4; j++){
            const int row = warp*4 + j;
            const int eid = base + j;
            ok[j] = (eid < E);
            if (ok[j]){
                sendi[j] = edge_index[eid];
                recvi[j] = edge_index[E + eid];
                #pragma unroll
                for (int n = 0; n < 5; n++) ef[j][n] = g_ef0[(size_t)eid*5 + n];
                float4 a = *(const float4*)&g_agg[(size_t)eid*FD + fo];
                cur[j] = *(const float4*)&g_e[(size_t)eid*FD + fo];
                stA_tf32(sAD, row, fo, a);
            } else {
                sendi[j] = 0; recvi[j] = 0;
                #pragma unroll
                for (int n = 0; n < 5; n++) ef[j][n] = 0.0f;
                cur[j] = zero4;
                stA_tf32(sAD, row, fo, zero4);
            }
            // prefetch stage-2 gathers; latency hidden behind stage-1/2 GEMMs
            pi_pre[j] = *(const float4*)&g_pi[(size_t)sendi[j]*FD + fo];
            pj_pre[j] = *(const float4*)&g_pj[(size_t)recvi[j]*FD + fo];
        }
        __syncthreads();

        // ---- stage 1: e1 = e + swish(agg @ Wtb + btb)
        gemm_compute(sWtb, sAD, warp, lane, c);
        __syncthreads();
        gemm_store(sADf, warp, lane, c);
        __syncthreads();
        {
            float4 b4 = *(const float4*)&sbtb[fo];
            #pragma unroll
            for (int j = 0; j < 4; j++){
                const int row = warp*4 + j;
                float4 d = ldD(sADf, row, fo);
                cur[j] = add4(cur[j], swish4(add4(d, b4)));
                stA_tf32(sAD, row, fo, cur[j]);
            }
        }
        __syncthreads();

        // ---- stage 2: e2 = e1 + swish(pi[s]+pj[r]+e1@We1e+be1) * (ef0@We0)
        gemm_compute(sWe1, sAD, warp, lane, c);
        __syncthreads();
        gemm_store(sADf, warp, lane, c);
        __syncthreads();
        float4 pai_pre[4], paj_pre[4];
        {
            float4 p0[4];
            #pragma unroll
            for (int j = 0; j < 4; j++) p0[j] = zero4;
            #pragma unroll
            for (int n = 0; n < 5; n++){
                float4 w = *(const float4*)&sWe0[n*FD + fo];
                #pragma unroll
                for (int j = 0; j < 4; j++) fma4(p0[j], ef[j][n], w);
            }
            float4 b4 = *(const float4*)&sbe1[fo];
            #pragma unroll
            for (int j = 0; j < 4; j++){
                const int row = warp*4 + j;
                float4 d = ldD(sADf, row, fo);
                float4 pre = make_float4(d.x+b4.x+pi_pre[j].x+pj_pre[j].x,
                                         d.y+b4.y+pi_pre[j].y+pj_pre[j].y,
                                         d.z+b4.z+pi_pre[j].z+pj_pre[j].z,
                                         d.w+b4.w+pi_pre[j].w+pj_pre[j].w);
                cur[j] = add4(cur[j], mul4(swish4(pre), p0[j]));
                if (ok[j]) *(float4*)&g_e[(size_t)(base+j)*FD + fo] = cur[j];
                // prefetch stage-3 gathers; hidden behind stage-3 GEMM
                pai_pre[j] = *(const float4*)&g_pai[(size_t)sendi[j]*FD + fo];
                paj_pre[j] = *(const float4*)&g_paj[(size_t)recvi[j]*FD + fo];
            }
        }
        __syncthreads();           // all D reads done before overwriting with A
        #pragma unroll
        for (int j = 0; j < 4; j++) stA_tf32(sAD, warp*4 + j, fo, cur[j]);
        __syncthreads();

        // ---- stage 3: v[recv] += swish(pai[s]+paj[r]+e2@Wa1e+ba1) * (ef0@Wa0)
        gemm_compute(sWa1, sAD, warp, lane, c);
        __syncthreads();
        gemm_store(sADf, warp, lane, c);
        __syncthreads();
        {
            float4 p0[4];
            #pragma unroll
            for (int j = 0; j < 4; j++) p0[j] = zero4;
            #pragma unroll
            for (int n = 0; n < 5; n++){
                float4 w = *(const float4*)&sWa0[n*FD + fo];
                #pragma unroll
                for (int j = 0; j < 4; j++) fma4(p0[j], ef[j][n], w);
            }
            float4 b4 = *(const float4*)&sba1[fo];
            #pragma unroll
            for (int j = 0; j < 4; j++){
                if (ok[j]){
                    const int row = warp*4 + j;
                    float4 d = ldD(sADf, row, fo);
                    float4 pre = make_float4(d.x+b4.x+pai_pre[j].x+paj_pre[j].x,
                                             d.y+b4.y+pai_pre[j].y+paj_pre[j].y,
                                             d.z+b4.z+pai_pre[j].z+paj_pre[j].z,
                                             d.w+b4.w+pai_pre[j].w+paj_pre[j].w);
                    float4 m = mul4(swish4(pre), p0[j]);
                    red4(&g_v[(size_t)recvi[j]*FD + fo], m);
                }
            }
        }
        __syncthreads();
    }
}

// ------------------- final readout MLP -------------------------------------
__global__ __launch_bounds__(128)
void k_final(const float* __restrict__ W1, const float* __restrict__ b1,
             const float* __restrict__ W2, const float* __restrict__ b2,
             const float* __restrict__ W3, const float* __restrict__ b3,
             float* __restrict__ out, int N)
{
    __shared__ float sv[FD];
    __shared__ float sh[FD];
    __shared__ float sred[4];
    int n = blockIdx.x;
    if (n >= N) return;
    int t = threadIdx.x;
    sv[t] = g_v[(size_t)n*FD + t];
    __syncthreads();
    float acc = b1[t];
    #pragma unroll 8
    for (int k = 0; k < FD; k++) acc = fmaf(sv[k], W1[k*FD + t], acc);
    sh[t] = swishf(acc);
    __syncthreads();
    acc = b2[t];
    #pragma unroll 8
    for (int k = 0; k < FD; k++) acc = fmaf(sh[k], W2[k*FD + t], acc);
    float prod = swishf(acc) * W3[t];
    #pragma unroll
    for (int o = 16; o > 0; o >>= 1) prod += __shfl_down_sync(0xffffffffu, prod, o);
    if ((t & 31) == 0) sred[t >> 5] = prod;
    __syncthreads();
    if (t == 0) out[n] = sred[0] + sred[1] + sred[2] + sred[3] + b3[0];
}

// ------------------------- launch ------------------------------------------
extern "C" void kernel_launch(void* const* d_in, const int* in_sizes, int n_in,
                              void* d_out, int out_size)
{
    const int*   atomic_numbers = (const int*  )d_in[0];
    const int*   edge_index     = (const int*  )d_in[1];
    const float* edge_dist      = (const float*)d_in[2];
    const int*   tbi            = (const int*  )d_in[3];
    const float* norm_ik        = (const float*)d_in[4];
    const float* cos_ang        = (const float*)d_in[5];
    const int*   tnb            = (const int*  )d_in[6];
    const int*   tna            = (const int*  )d_in[7];
    const float* emb            = (const float*)d_in[8];
    const float* W_enc          = (const float*)d_in[9];
    const float* b_enc          = (const float*)d_in[10];
    const float* W_angle        = (const float*)d_in[11];
    const float* Wg             = (const float*)d_in[12];
    const float* bg             = (const float*)d_in[13];
    const float* W_tb           = (const float*)d_in[14];
    const float* b_tb           = (const float*)d_in[15];
    const float* We1            = (const float*)d_in[16];
    const float* be1            = (const float*)d_in[17];
    const float* We0            = (const float*)d_in[18];
    const float* Wa1            = (const float*)d_in[19];
    const float* ba1            = (const float*)d_in[20];
    const float* Wa0            = (const float*)d_in[21];
    const float* W1             = (const float*)d_in[22];
    const float* b1             = (const float*)d_in[23];
    const float* W2             = (const float*)d_in[24];
    const float* b2             = (const float*)d_in[25];
    const float* W3             = (const float*)d_in[26];
    const float* b3             = (const float*)d_in[27];

    const int N = in_sizes[0];
    const int E = in_sizes[2];
    const int A = in_sizes[4];
    const int G = in_sizes[6];
    float* out = (float*)d_out;

    cudaFuncSetAttribute(k_edge_fused, cudaFuncAttributeMaxDynamicSharedMemorySize,
                         SMEM_EDGE_BYTES);

    float* aggp = nullptr;
    cudaGetSymbolAddress((void**)&aggp, g_agg);

    k_offsets  <<<1, 32>>>(tnb, tna, G);
    k_angle_pre<<<(A + 255) / 256, 256>>>(tbi, norm_ik, cos_ang, edge_index, A, E, G);
    k_edge_init<<<(E + 3) / 4, 128>>>(edge_dist, W_enc, b_enc, E);
    k_vinit    <<<(N * 32 + 255) / 256, 256>>>(atomic_numbers, emb, N);

    for (int b = 0; b < 4; b++){
        cudaMemsetAsync(aggp, 0, (size_t)E * FD * sizeof(float), 0);
        k_gate_pre<<<(N + 7) / 8, 256>>>(Wg + (size_t)b*FD*FD, bg + (size_t)b*FD,
                                         We1 + (size_t)b*3*FD*FD, Wa1 + (size_t)b*3*FD*FD, N);
        k_angle<<<1184, 256>>>(W_angle + (size_t)b*16*FD, A);
        k_edge_fused<<<EDGE_GRID, 256, SMEM_EDGE_BYTES>>>(
            W_tb + (size_t)b*FD*FD,            b_tb + (size_t)b*FD,
            We1  + (size_t)b*3*FD*FD + 2*FD*FD, be1 + (size_t)b*FD,
            We0  + (size_t)b*5*FD,
            Wa1  + (size_t)b*3*FD*FD + 2*FD*FD, ba1 + (size_t)b*FD,
            Wa0  + (size_t)b*5*FD,
            edge_index, E);
    }

    k_final<<<N, 128>>>(W1, b1, W2, b2, W3, b3, out, N);
}

// round 15
// speedup vs baseline: 2.0048x; 1.1377x over previous
#include <cuda_runtime.h>
#include <math.h>
#include <stdint.h>

#define FD   128
#define EMAX 200000
#define NMAX 8000
#define AMAX 400000
#define GMAX 128
#define PI_F 3.14159265358979323846f

// ------------------------- scratch (device globals; no allocs) -------------
__device__ float g_e   [(size_t)EMAX * FD];
__device__ float g_agg [(size_t)EMAX * FD];
__device__ float g_ef0 [(size_t)EMAX * 5];
__device__ float g_v   [(size_t)NMAX * FD];
__device__ float g_gate[(size_t)NMAX * FD];
__device__ float g_pi  [(size_t)NMAX * FD];
__device__ float g_pj  [(size_t)NMAX * FD];
__device__ float g_pai [(size_t)NMAX * FD];
__device__ float g_paj [(size_t)NMAX * FD];
__device__ float g_angf[(size_t)AMAX * 16];
__device__ int   g_iij [AMAX];
__device__ int   g_kat [AMAX];
__device__ int   g_boff[GMAX];
__device__ int   g_acum[GMAX + 1];

// ------------------------- helpers ----------------------------------------
__device__ __forceinline__ void fma4(float4& a, float s, float4 b){
    a.x = fmaf(s, b.x, a.x);
    a.y = fmaf(s, b.y, a.y);
    a.z = fmaf(s, b.z, a.z);
    a.w = fmaf(s, b.w, a.w);
}
__device__ __forceinline__ float sigmf(float x){ return __fdividef(1.0f, 1.0f + __expf(-x)); }
__device__ __forceinline__ float swishf(float x){ return x * sigmf(x); }
__device__ __forceinline__ float4 swish4(float4 a){
    return make_float4(swishf(a.x), swishf(a.y), swishf(a.z), swishf(a.w));
}
__device__ __forceinline__ float4 sigm4(float4 a){
    return make_float4(sigmf(a.x), sigmf(a.y), sigmf(a.z), sigmf(a.w));
}
__device__ __forceinline__ float4 add4(float4 a, float4 b){
    return make_float4(a.x+b.x, a.y+b.y, a.z+b.z, a.w+b.w);
}
__device__ __forceinline__ float4 mul4(float4 a, float4 b){
    return make_float4(a.x*b.x, a.y*b.y, a.z*b.z, a.w*b.w);
}
__device__ __forceinline__ void red4(float* p, float4 v){
    asm volatile("red.global.add.v4.f32 [%0], {%1,%2,%3,%4};"
                 :: "l"(p), "f"(v.x), "f"(v.y), "f"(v.z), "f"(v.w) : "memory");
}
// pack (lo, hi) floats -> bf16x2 (lo in low half)
__device__ __forceinline__ uint32_t bf2pack(float lo, float hi){
    uint32_t r; asm("cvt.rn.bf16x2.f32 %0, %1, %2;" : "=r"(r) : "f"(hi), "f"(lo)); return r;
}
__device__ __forceinline__ void mma_bf16(float c[4],
    uint32_t a0, uint32_t a1, uint32_t a2, uint32_t a3,
    uint32_t b0, uint32_t b1)
{
    asm volatile(
        "mma.sync.aligned.m16n8k16.row.col.f32.bf16.bf16.f32 "
        "{%0,%1,%2,%3}, {%4,%5,%6,%7}, {%8,%9}, {%0,%1,%2,%3};"
        : "+f"(c[0]), "+f"(c[1]), "+f"(c[2]), "+f"(c[3])
        : "r"(a0), "r"(a1), "r"(a2), "r"(a3), "r"(b0), "r"(b1));
}

// ------------------------- prep kernels ------------------------------------
__global__ void k_offsets(const int* __restrict__ tnb, const int* __restrict__ tna, int G){
    if (threadIdx.x == 0 && blockIdx.x == 0){
        int ob = 0, oa = 0;
        g_acum[0] = 0;
        for (int g = 0; g < G; g++){
            g_boff[g] = ob;
            ob += tnb[g];
            oa += tna[g];
            g_acum[g + 1] = oa;
        }
    }
}

__global__ void k_angle_pre(const int* __restrict__ tbi,
                            const float* __restrict__ norm_ik,
                            const float* __restrict__ cosang,
                            const int* __restrict__ edge_index,
                            int A, int E, int G)
{
    int a = blockIdx.x * blockDim.x + threadIdx.x;
    if (a >= A) return;
    int lo = 0, hi = G - 1;
    while (lo < hi){ int mid = (lo + hi + 1) >> 1; if (g_acum[mid] <= a) lo = mid; else hi = mid - 1; }
    int off = g_boff[lo];
    int iij = tbi[2*a]     + off;
    int iik = tbi[2*a + 1] + off;
    g_iij[a] = iij;
    g_kat[a] = edge_index[E + iik];

    float r = norm_ik[a];
    float c = cosang[a];
    float x = r * 0.25f;
    float x2 = x*x, x3 = x2*x;
    float fc = 1.0f - 6.0f*x3*x2 + 15.0f*x2*x2 - 10.0f*x3;
    float invr = 1.0f / r;
    float s2 = fc * fc * invr;
    float rad[4];
    #pragma unroll
    for (int n = 0; n < 4; n++) rad[n] = sinf((float)(n+1) * PI_F * x) * s2;
    float P0 = 1.0f, P1 = c;
    float P2 = 0.5f * (3.0f*c*c - 1.0f);
    float P3 = 0.5f * c * (5.0f*c*c - 3.0f);
    #pragma unroll
    for (int n = 0; n < 4; n++)
        *(float4*)&g_angf[(size_t)a*16 + n*4] = make_float4(rad[n]*P0, rad[n]*P1, rad[n]*P2, rad[n]*P3);
}

__global__ void k_edge_init(const float* __restrict__ edge_dist,
                            const float* __restrict__ W_enc,
                            const float* __restrict__ b_enc, int E)
{
    int gw   = (blockIdx.x * blockDim.x + threadIdx.x) >> 5;
    int lane = threadIdx.x & 31;
    if (gw >= E) return;
    float r    = edge_dist[gw];
    float invr = 1.0f / r;
    const float C = sqrtf(2.0f / 5.0f);
    float ef[5];
    #pragma unroll
    for (int n = 0; n < 5; n++) ef[n] = C * sinf((float)(n+1) * PI_F * r * 0.2f) * invr;
    if (lane < 5) g_ef0[(size_t)gw*5 + lane] = ef[lane];
    int fo = lane * 4;
    float4 acc = *(const float4*)&b_enc[fo];
    #pragma unroll
    for (int n = 0; n < 5; n++){
        float4 w = *(const float4*)&W_enc[n*FD + fo];
        fma4(acc, ef[n], w);
    }
    *(float4*)&g_e[(size_t)gw*FD + fo] = swish4(acc);
}

__global__ void k_vinit(const int* __restrict__ z, const float* __restrict__ emb, int N){
    int t = blockIdx.x * blockDim.x + threadIdx.x;
    if (t >= N * 32) return;
    int n = t >> 5, fo = (t & 31) * 4;
    *(float4*)&g_v[(size_t)n*FD + fo] = *(const float4*)&emb[(size_t)z[n]*FD + fo];
}

// ------------------- per-block: atom precompute (gate + concat parts) -------
__global__ __launch_bounds__(256)
void k_gate_pre(const float* __restrict__ Wg,  const float* __restrict__ bg,
                const float* __restrict__ We1b, const float* __restrict__ Wa1b, int N)
{
    __shared__ float sv[8][FD];
    const int warp = threadIdx.x >> 5, lane = threadIdx.x & 31;
    const int fo = lane * 4;
    for (int base = blockIdx.x * 8; base < N; base += gridDim.x * 8){
        int na = N - base; if (na > 8) na = 8;
        __syncthreads();
        for (int idx = threadIdx.x; idx < na * 32; idx += blockDim.x){
            int rr = idx >> 5, cc = (idx & 31) * 4;
            *(float4*)&sv[rr][cc] = *(const float4*)&g_v[(size_t)(base+rr)*FD + cc];
        }
        __syncthreads();
        if (warp < 5){
            const float* W = (warp == 0) ? Wg
                           : (warp == 1) ? We1b
                           : (warp == 2) ? (We1b + FD*FD)
                           : (warp == 3) ? Wa1b
                           :               (Wa1b + FD*FD);
            float4 acc[8];
            #pragma unroll
            for (int j = 0; j < 8; j++) acc[j] = make_float4(0,0,0,0);
            #pragma unroll 4
            for (int k4 = 0; k4 < 32; k4++){
                float4 w0 = *(const float4*)&W[(k4*4+0)*FD + fo];
                float4 w1 = *(const float4*)&W[(k4*4+1)*FD + fo];
                float4 w2 = *(const float4*)&W[(k4*4+2)*FD + fo];
                float4 w3 = *(const float4*)&W[(k4*4+3)*FD + fo];
                #pragma unroll
                for (int j = 0; j < 8; j++){
                    float4 s = *(const float4*)&sv[j][k4*4];
                    fma4(acc[j], s.x, w0); fma4(acc[j], s.y, w1);
                    fma4(acc[j], s.z, w2); fma4(acc[j], s.w, w3);
                }
            }
            if (warp == 0){
                float4 b4 = *(const float4*)&bg[fo];
                for (int j = 0; j < na; j++)
                    *(float4*)&g_gate[(size_t)(base+j)*FD + fo] = sigm4(add4(acc[j], b4));
            } else {
                float* dst = (warp == 1) ? g_pi : (warp == 2) ? g_pj : (warp == 3) ? g_pai : g_paj;
                for (int j = 0; j < na; j++)
                    *(float4*)&dst[(size_t)(base+j)*FD + fo] = acc[j];
            }
        }
    }
}

// ------------------- per-block: angle message scatter -----------------------
__global__ __launch_bounds__(256)
void k_angle(const float* __restrict__ Wang, int A)
{
    __shared__ float sW[16 * FD];
    for (int i = threadIdx.x; i < 16*FD/4; i += blockDim.x)
        ((float4*)sW)[i] = ((const float4*)Wang)[i];
    __syncthreads();
    const int lane = threadIdx.x & 31;
    const int fo = lane * 4;
    int gw = (blockIdx.x * blockDim.x + threadIdx.x) >> 5;
    int nw = (gridDim.x * blockDim.x) >> 5;
    for (int a = gw; a < A; a += nw){
        int iij = g_iij[a], kat = g_kat[a];
        const float4* af = (const float4*)&g_angf[(size_t)a*16];
        float4 acc = make_float4(0,0,0,0);
        #pragma unroll
        for (int k4 = 0; k4 < 4; k4++){
            float4 s  = af[k4];
            float4 w0 = *(const float4*)&sW[(k4*4+0)*FD + fo];
            float4 w1 = *(const float4*)&sW[(k4*4+1)*FD + fo];
            float4 w2 = *(const float4*)&sW[(k4*4+2)*FD + fo];
            float4 w3 = *(const float4*)&sW[(k4*4+3)*FD + fo];
            fma4(acc, s.x, w0); fma4(acc, s.y, w1); fma4(acc, s.z, w2); fma4(acc, s.w, w3);
        }
        float4 g = *(const float4*)&g_gate[(size_t)kat*FD + fo];
        red4(&g_agg[(size_t)iij*FD + fo], mul4(acc, g));
    }
}

// ------------------- per-block: fused edge update, bf16 MMA, 8 warps --------
// 256 threads, TILE_E=32 edges per CTA iteration, grid <= 148 (1 CTA/SM).
// Weights bf16-packed [k/2][col] (32KB each); A bf16-packed [row][k/2] (8KB);
// D fp32 [row][col] (16KB) in its OWN buffer -> no compute/store hazard.
#define TILE_E 32
#define EDGE_GRID 148
#define SMEM_EDGE_BYTES ((3*64*128 + 32*64 + 32*128 + 2*5*FD + 3*FD) * 4)

// A pair-index swizzle: fully conflict-free for fragment loads (verified:
// bank XOR set {0,8,16,24,4,12,20,28} distinct across gid 0..7)
__device__ __forceinline__ int szA(int row){
    return ((row & 7) * 8) ^ (((row >> 2) & 1) * 4);
}

// compute: c = A[32x128] @ W[128x128] (bf16 in, fp32 accum)
__device__ __forceinline__ void gemm_compute(const uint32_t* __restrict__ sW,
                                             const uint32_t* __restrict__ sA,
                                             int warp, int lane, float c[4][4])
{
    const int rt  = warp >> 2;          // row-tile 0..1 (m16)
    const int cw  = warp & 3;           // coltile group: n8 tiles cw*4+i
    const int gid = lane >> 2;          // 0..7
    const int t   = lane & 3;           // 0..3
    const int r0  = rt*16 + gid, r1 = r0 + 8;
    const int sza = szA(r0);            // equal for r0 and r1 (differ by 8)
    #pragma unroll
    for (int i = 0; i < 4; i++){ c[i][0]=0.f; c[i][1]=0.f; c[i][2]=0.f; c[i][3]=0.f; }
    #pragma unroll
    for (int kk = 0; kk < 8; kk++){     // k16 steps
        const int p0 = kk*8 + t;        // bf16-pair index (k/2)
        const int p1 = p0 + 4;
        uint32_t a0 = sA[r0*64 + (p0 ^ sza)];
        uint32_t a1 = sA[r1*64 + (p0 ^ sza)];
        uint32_t a2 = sA[r0*64 + (p1 ^ sza)];
        uint32_t a3 = sA[r1*64 + (p1 ^ sza)];
        #pragma unroll
        for (int i = 0; i < 4; i++){
            const int col = (cw*4 + i)*8 + gid;
            uint32_t b0 = sW[p0*128 + (col ^ (t*8))];   // (p0&3)==t
            uint32_t b1 = sW[p1*128 + (col ^ (t*8))];   // (p1&3)==t
            mma_bf16(c[i], a0, a1, a2, a3, b0, b1);
        }
    }
}

__device__ __forceinline__ void gemm_store(float* __restrict__ sD,
                                           int warp, int lane, const float c[4][4])
{
    const int rt  = warp >> 2;
    const int cw  = warp & 3;
    const int gid = lane >> 2;
    const int t   = lane & 3;
    const int r0  = rt*16 + gid, r1 = r0 + 8;
    const int sz  = (gid & 3) * 8;
    #pragma unroll
    for (int i = 0; i < 4; i++){
        const int colb = (cw*4 + i)*8 + 2*t;
        *(float2*)&sD[r0*128 + (colb ^ sz)] = make_float2(c[i][0], c[i][1]);
        *(float2*)&sD[r1*128 + (colb ^ sz)] = make_float2(c[i][2], c[i][3]);
    }
}

__device__ __forceinline__ void stA_bf16(uint32_t* __restrict__ sA, int row, int lane, float4 v){
    const int p  = lane * 2;            // pair index of fo
    const int sz = szA(row);
    uint2 u = make_uint2(bf2pack(v.x, v.y), bf2pack(v.z, v.w));
    *(uint2*)&sA[row*64 + (p ^ sz)] = u;   // p even, sz bit0=0 -> 8B aligned
}
__device__ __forceinline__ float4 ldD(const float* __restrict__ sD, int row, int fo){
    return *(const float4*)&sD[row*128 + (fo ^ ((row & 3)*8))];
}

__global__ __launch_bounds__(256, 1)
void k_edge_fused(const float* __restrict__ Wtb,  const float* __restrict__ btb,
                  const float* __restrict__ We1e, const float* __restrict__ be1,
                  const float* __restrict__ We0,
                  const float* __restrict__ Wa1e, const float* __restrict__ ba1,
                  const float* __restrict__ Wa0,
                  const int* __restrict__ edge_index, int E)
{
    extern __shared__ char smraw[];
    uint32_t* sWtb = (uint32_t*)smraw;          // 64x128 u32 (bf16x2)
    uint32_t* sWe1 = sWtb + 64*128;
    uint32_t* sWa1 = sWe1 + 64*128;
    uint32_t* sA   = sWa1 + 64*128;             // 32x64 u32 (bf16x2)
    float*    sD   = (float*)(sA + 32*64);      // 32x128 f32
    float*    sWe0 = sD + 32*128;
    float*    sWa0 = sWe0 + 5*FD;
    float*    sbtb = sWa0 + 5*FD;
    float*    sbe1 = sbtb + FD;
    float*    sba1 = sbe1 + FD;

    // load + bf16-pack + swizzle weights: sW[p][col ^ (p&3)*8] = (W[2p][c], W[2p+1][c])
    for (int i = threadIdx.x; i < FD*FD/2; i += blockDim.x){
        int p = i >> 7, col = i & 127;
        int dst = p*128 + (col ^ ((p & 3)*8));
        sWtb[dst] = bf2pack(Wtb [(2*p)*FD + col], Wtb [(2*p+1)*FD + col]);
        sWe1[dst] = bf2pack(We1e[(2*p)*FD + col], We1e[(2*p+1)*FD + col]);
        sWa1[dst] = bf2pack(Wa1e[(2*p)*FD + col], Wa1e[(2*p+1)*FD + col]);
    }
    for (int i = threadIdx.x; i < 5*FD; i += blockDim.x){
        sWe0[i] = We0[i];
        sWa0[i] = Wa0[i];
    }
    if (threadIdx.x < FD){
        sbtb[threadIdx.x] = btb[threadIdx.x];
        sbe1[threadIdx.x] = be1[threadIdx.x];
        sba1[threadIdx.x] = ba1[threadIdx.x];
    }
    __syncthreads();

    const int warp = threadIdx.x >> 5;
    const int lane = threadIdx.x & 31;
    const int fo = lane * 4;
    const float4 zero4 = make_float4(0,0,0,0);
    float c[4][4];

    for (int base0 = blockIdx.x * TILE_E; base0 < E; base0 += gridDim.x * TILE_E){
        const int base = base0 + warp * 4;   // warp owns rows warp*4..warp*4+3

        int sendi[4], recvi[4];
        bool ok[4];
        float ef[4][5];
        float4 cur[4];
        float4 pi_pre[4], pj_pre[4];
        #pragma unroll
        for (int j = 0; j < 4; j++){
            const int row = warp*4 + j;
            const int eid = base + j;
            ok[j] = (eid < E);
            if (ok[j]){
                sendi[j] = edge_index[eid];
                recvi[j] = edge_index[E + eid];
                #pragma unroll
                for (int n = 0; n < 5; n++) ef[j][n] = g_ef0[(size_t)eid*5 + n];
                float4 a = *(const float4*)&g_agg[(size_t)eid*FD + fo];
                cur[j] = *(const float4*)&g_e[(size_t)eid*FD + fo];
                stA_bf16(sA, row, lane, a);
            } else {
                sendi[j] = 0; recvi[j] = 0;
                #pragma unroll
                for (int n = 0; n < 5; n++) ef[j][n] = 0.0f;
                cur[j] = zero4;
                stA_bf16(sA, row, lane, zero4);
            }
            // prefetch stage-2 gathers; latency hidden behind stage-1/2 GEMMs
            pi_pre[j] = *(const float4*)&g_pi[(size_t)sendi[j]*FD + fo];
            pj_pre[j] = *(const float4*)&g_pj[(size_t)recvi[j]*FD + fo];
        }
        __syncthreads();

        // ---- stage 1: e1 = e + swish(agg @ Wtb + btb)
        gemm_compute(sWtb, sA, warp, lane, c);
        gemm_store(sD, warp, lane, c);          // D separate: no pre-store sync
        __syncthreads();
        {
            float4 b4 = *(const float4*)&sbtb[fo];
            #pragma unroll
            for (int j = 0; j < 4; j++){
                const int row = warp*4 + j;
                float4 d = ldD(sD, row, fo);
                cur[j] = add4(cur[j], swish4(add4(d, b4)));
                stA_bf16(sA, row, lane, cur[j]);
            }
        }
        __syncthreads();

        // ---- stage 2: e2 = e1 + swish(pi[s]+pj[r]+e1@We1e+be1) * (ef0@We0)
        gemm_compute(sWe1, sA, warp, lane, c);
        gemm_store(sD, warp, lane, c);
        __syncthreads();
        float4 pai_pre[4], paj_pre[4];
        {
            float4 p0[4];
            #pragma unroll
            for (int j = 0; j < 4; j++) p0[j] = zero4;
            #pragma unroll
            for (int n = 0; n < 5; n++){
                float4 w = *(const float4*)&sWe0[n*FD + fo];
                #pragma unroll
                for (int j = 0; j < 4; j++) fma4(p0[j], ef[j][n], w);
            }
            float4 b4 = *(const float4*)&sbe1[fo];
            #pragma unroll
            for (int j = 0; j < 4; j++){
                const int row = warp*4 + j;
                float4 d = ldD(sD, row, fo);
                float4 pre = make_float4(d.x+b4.x+pi_pre[j].x+pj_pre[j].x,
                                         d.y+b4.y+pi_pre[j].y+pj_pre[j].y,
                                         d.z+b4.z+pi_pre[j].z+pj_pre[j].z,
                                         d.w+b4.w+pi_pre[j].w+pj_pre[j].w);
                cur[j] = add4(cur[j], mul4(swish4(pre), p0[j]));
                if (ok[j]) *(float4*)&g_e[(size_t)(base+j)*FD + fo] = cur[j];
                stA_bf16(sA, row, lane, cur[j]);
                // prefetch stage-3 gathers; hidden behind stage-3 GEMM
                pai_pre[j] = *(const float4*)&g_pai[(size_t)sendi[j]*FD + fo];
                paj_pre[j] = *(const float4*)&g_paj[(size_t)recvi[j]*FD + fo];
            }
        }
        __syncthreads();

        // ---- stage 3: v[recv] += swish(pai[s]+paj[r]+e2@Wa1e+ba1) * (ef0@Wa0)
        gemm_compute(sWa1, sA, warp, lane, c);
        gemm_store(sD, warp, lane, c);
        __syncthreads();
        {
            float4 p0[4];
            #pragma unroll
            for (int j = 0; j < 4; j++) p0[j] = zero4;
            #pragma unroll
            for (int n = 0; n < 5; n++){
                float4 w = *(const float4*)&sWa0[n*FD + fo];
                #pragma unroll
                for (int j = 0; j < 4; j++) fma4(p0[j], ef[j][n], w);
            }
            float4 b4 = *(const float4*)&sba1[fo];
            #pragma unroll
            for (int j = 0; j < 4; j++){
                if (ok[j]){
                    const int row = warp*4 + j;
                    float4 d = ldD(sD, row, fo);
                    float4 pre = make_float4(d.x+b4.x+pai_pre[j].x+paj_pre[j].x,
                                             d.y+b4.y+pai_pre[j].y+paj_pre[j].y,
                                             d.z+b4.z+pai_pre[j].z+paj_pre[j].z,
                                             d.w+b4.w+pai_pre[j].w+paj_pre[j].w);
                    float4 m = mul4(swish4(pre), p0[j]);
                    red4(&g_v[(size_t)recvi[j]*FD + fo], m);
                }
            }
        }
        __syncthreads();   // D reads done before next tile's gemm_store; A before stA
    }
}

// ------------------- final readout MLP -------------------------------------
__global__ __launch_bounds__(128)
void k_final(const float* __restrict__ W1, const float* __restrict__ b1,
             const float* __restrict__ W2, const float* __restrict__ b2,
             const float* __restrict__ W3, const float* __restrict__ b3,
             float* __restrict__ out, int N)
{
    __shared__ float sv[FD];
    __shared__ float sh[FD];
    __shared__ float sred[4];
    int n = blockIdx.x;
    if (n >= N) return;
    int t = threadIdx.x;
    sv[t] = g_v[(size_t)n*FD + t];
    __syncthreads();
    float acc = b1[t];
    #pragma unroll 8
    for (int k = 0; k < FD; k++) acc = fmaf(sv[k], W1[k*FD + t], acc);
    sh[t] = swishf(acc);
    __syncthreads();
    acc = b2[t];
    #pragma unroll 8
    for (int k = 0; k < FD; k++) acc = fmaf(sh[k], W2[k*FD + t], acc);
    float prod = swishf(acc) * W3[t];
    #pragma unroll
    for (int o = 16; o > 0; o >>= 1) prod += __shfl_down_sync(0xffffffffu, prod, o);
    if ((t & 31) == 0) sred[t >> 5] = prod;
    __syncthreads();
    if (t == 0) out[n] = sred[0] + sred[1] + sred[2] + sred[3] + b3[0];
}

// ------------------------- launch ------------------------------------------
extern "C" void kernel_launch(void* const* d_in, const int* in_sizes, int n_in,
                              void* d_out, int out_size)
{
    const int*   atomic_numbers = (const int*  )d_in[0];
    const int*   edge_index     = (const int*  )d_in[1];
    const float* edge_dist      = (const float*)d_in[2];
    const int*   tbi            = (const int*  )d_in[3];
    const float* norm_ik        = (const float*)d_in[4];
    const float* cos_ang        = (const float*)d_in[5];
    const int*   tnb            = (const int*  )d_in[6];
    const int*   tna            = (const int*  )d_in[7];
    const float* emb            = (const float*)d_in[8];
    const float* W_enc          = (const float*)d_in[9];
    const float* b_enc          = (const float*)d_in[10];
    const float* W_angle        = (const float*)d_in[11];
    const float* Wg             = (const float*)d_in[12];
    const float* bg             = (const float*)d_in[13];
    const float* W_tb           = (const float*)d_in[14];
    const float* b_tb           = (const float*)d_in[15];
    const float* We1            = (const float*)d_in[16];
    const float* be1            = (const float*)d_in[17];
    const float* We0            = (const float*)d_in[18];
    const float* Wa1            = (const float*)d_in[19];
    const float* ba1            = (const float*)d_in[20];
    const float* Wa0            = (const float*)d_in[21];
    const float* W1             = (const float*)d_in[22];
    const float* b1             = (const float*)d_in[23];
    const float* W2             = (const float*)d_in[24];
    const float* b2             = (const float*)d_in[25];
    const float* W3             = (const float*)d_in[26];
    const float* b3             = (const float*)d_in[27];

    const int N = in_sizes[0];
    const int E = in_sizes[2];
    const int A = in_sizes[4];
    const int G = in_sizes[6];
    float* out = (float*)d_out;

    cudaFuncSetAttribute(k_edge_fused, cudaFuncAttributeMaxDynamicSharedMemorySize,
                         SMEM_EDGE_BYTES);

    float* aggp = nullptr;
    cudaGetSymbolAddress((void**)&aggp, g_agg);

    k_offsets  <<<1, 32>>>(tnb, tna, G);
    k_angle_pre<<<(A + 255) / 256, 256>>>(tbi, norm_ik, cos_ang, edge_index, A, E, G);
    k_edge_init<<<(E + 3) / 4, 128>>>(edge_dist, W_enc, b_enc, E);
    k_vinit    <<<(N * 32 + 255) / 256, 256>>>(atomic_numbers, emb, N);

    for (int b = 0; b < 4; b++){
        cudaMemsetAsync(aggp, 0, (size_t)E * FD * sizeof(float), 0);
        k_gate_pre<<<(N + 7) / 8, 256>>>(Wg + (size_t)b*FD*FD, bg + (size_t)b*FD,
                                         We1 + (size_t)b*3*FD*FD, Wa1 + (size_t)b*3*FD*FD, N);
        k_angle<<<1184, 256>>>(W_angle + (size_t)b*16*FD, A);
        k_edge_fused<<<EDGE_GRID, 256, SMEM_EDGE_BYTES>>>(
            W_tb + (size_t)b*FD*FD,            b_tb + (size_t)b*FD,
            We1  + (size_t)b*3*FD*FD + 2*FD*FD, be1 + (size_t)b*FD,
            We0  + (size_t)b*5*FD,
            Wa1  + (size_t)b*3*FD*FD + 2*FD*FD, ba1 + (size_t)b*FD,
            Wa0  + (size_t)b*5*FD,
            edge_index, E);
    }

    k_final<<<N, 128>>>(W1, b1, W2, b2, W3, b3, out, N);
}

// round 16
// speedup vs baseline: 2.6379x; 1.3158x over previous
#include <cuda_runtime.h>
#include <math.h>
#include <stdint.h>

#define FD   128
#define EMAX 200000
#define NMAX 8000
#define AMAX 400000
#define GMAX 128
#define PI_F 3.14159265358979323846f

// ------------------------- scratch (device globals; no allocs) -------------
__device__ float g_e   [(size_t)EMAX * FD];
__device__ float g_agg [(size_t)EMAX * FD];
__device__ float g_ef0 [(size_t)EMAX * 5];
__device__ float g_v   [(size_t)NMAX * FD];
__device__ float g_gate[(size_t)NMAX * FD];
__device__ float g_pi  [(size_t)NMAX * FD];
__device__ float g_pj  [(size_t)NMAX * FD];
__device__ float g_pai [(size_t)NMAX * FD];
__device__ float g_paj [(size_t)NMAX * FD];
__device__ float g_angf[(size_t)AMAX * 16];
__device__ int   g_iij [AMAX];
__device__ int   g_kat [AMAX];
__device__ int   g_boff[GMAX];
__device__ int   g_acum[GMAX + 1];

// ------------------------- helpers ----------------------------------------
__device__ __forceinline__ void fma4(float4& a, float s, float4 b){
    a.x = fmaf(s, b.x, a.x);
    a.y = fmaf(s, b.y, a.y);
    a.z = fmaf(s, b.z, a.z);
    a.w = fmaf(s, b.w, a.w);
}
__device__ __forceinline__ float sigmf(float x){ return __fdividef(1.0f, 1.0f + __expf(-x)); }
__device__ __forceinline__ float swishf(float x){ return x * sigmf(x); }
__device__ __forceinline__ float4 swish4(float4 a){
    return make_float4(swishf(a.x), swishf(a.y), swishf(a.z), swishf(a.w));
}
__device__ __forceinline__ float4 sigm4(float4 a){
    return make_float4(sigmf(a.x), sigmf(a.y), sigmf(a.z), sigmf(a.w));
}
__device__ __forceinline__ float4 add4(float4 a, float4 b){
    return make_float4(a.x+b.x, a.y+b.y, a.z+b.z, a.w+b.w);
}
__device__ __forceinline__ float4 mul4(float4 a, float4 b){
    return make_float4(a.x*b.x, a.y*b.y, a.z*b.z, a.w*b.w);
}
__device__ __forceinline__ void red4(float* p, float4 v){
    asm volatile("red.global.add.v4.f32 [%0], {%1,%2,%3,%4};"
                 :: "l"(p), "f"(v.x), "f"(v.y), "f"(v.z), "f"(v.w) : "memory");
}
// pack (lo, hi) floats -> bf16x2 (lo in low half)
__device__ __forceinline__ uint32_t bf2pack(float lo, float hi){
    uint32_t r; asm("cvt.rn.bf16x2.f32 %0, %1, %2;" : "=r"(r) : "f"(hi), "f"(lo)); return r;
}
__device__ __forceinline__ void mma_bf16(float c[4],
    uint32_t a0, uint32_t a1, uint32_t a2, uint32_t a3,
    uint32_t b0, uint32_t b1)
{
    asm volatile(
        "mma.sync.aligned.m16n8k16.row.col.f32.bf16.bf16.f32 "
        "{%0,%1,%2,%3}, {%4,%5,%6,%7}, {%8,%9}, {%0,%1,%2,%3};"
        : "+f"(c[0]), "+f"(c[1]), "+f"(c[2]), "+f"(c[3])
        : "r"(a0), "r"(a1), "r"(a2), "r"(a3), "r"(b0), "r"(b1));
}

// ------------------------- prep kernels ------------------------------------
__global__ void k_offsets(const int* __restrict__ tnb, const int* __restrict__ tna, int G){
    if (threadIdx.x == 0 && blockIdx.x == 0){
        int ob = 0, oa = 0;
        g_acum[0] = 0;
        for (int g = 0; g < G; g++){
            g_boff[g] = ob;
            ob += tnb[g];
            oa += tna[g];
            g_acum[g + 1] = oa;
        }
    }
}

__global__ void k_angle_pre(const int* __restrict__ tbi,
                            const float* __restrict__ norm_ik,
                            const float* __restrict__ cosang,
                            const int* __restrict__ edge_index,
                            int A, int E, int G)
{
    int a = blockIdx.x * blockDim.x + threadIdx.x;
    if (a >= A) return;
    int lo = 0, hi = G - 1;
    while (lo < hi){ int mid = (lo + hi + 1) >> 1; if (g_acum[mid] <= a) lo = mid; else hi = mid - 1; }
    int off = g_boff[lo];
    int iij = tbi[2*a]     + off;
    int iik = tbi[2*a + 1] + off;
    g_iij[a] = iij;
    g_kat[a] = edge_index[E + iik];

    float r = norm_ik[a];
    float c = cosang[a];
    float x = r * 0.25f;
    float x2 = x*x, x3 = x2*x;
    float fc = 1.0f - 6.0f*x3*x2 + 15.0f*x2*x2 - 10.0f*x3;
    float invr = 1.0f / r;
    float s2 = fc * fc * invr;
    float rad[4];
    #pragma unroll
    for (int n = 0; n < 4; n++) rad[n] = sinf((float)(n+1) * PI_F * x) * s2;
    float P0 = 1.0f, P1 = c;
    float P2 = 0.5f * (3.0f*c*c - 1.0f);
    float P3 = 0.5f * c * (5.0f*c*c - 3.0f);
    #pragma unroll
    for (int n = 0; n < 4; n++)
        *(float4*)&g_angf[(size_t)a*16 + n*4] = make_float4(rad[n]*P0, rad[n]*P1, rad[n]*P2, rad[n]*P3);
}

__global__ void k_edge_init(const float* __restrict__ edge_dist,
                            const float* __restrict__ W_enc,
                            const float* __restrict__ b_enc, int E)
{
    int gw   = (blockIdx.x * blockDim.x + threadIdx.x) >> 5;
    int lane = threadIdx.x & 31;
    if (gw >= E) return;
    float r    = edge_dist[gw];
    float invr = 1.0f / r;
    const float C = sqrtf(2.0f / 5.0f);
    float ef[5];
    #pragma unroll
    for (int n = 0; n < 5; n++) ef[n] = C * sinf((float)(n+1) * PI_F * r * 0.2f) * invr;
    if (lane < 5) g_ef0[(size_t)gw*5 + lane] = ef[lane];
    int fo = lane * 4;
    float4 acc = *(const float4*)&b_enc[fo];
    #pragma unroll
    for (int n = 0; n < 5; n++){
        float4 w = *(const float4*)&W_enc[n*FD + fo];
        fma4(acc, ef[n], w);
    }
    *(float4*)&g_e[(size_t)gw*FD + fo] = swish4(acc);
}

__global__ void k_vinit(const int* __restrict__ z, const float* __restrict__ emb, int N){
    int t = blockIdx.x * blockDim.x + threadIdx.x;
    if (t >= N * 32) return;
    int n = t >> 5, fo = (t & 31) * 4;
    *(float4*)&g_v[(size_t)n*FD + fo] = *(const float4*)&emb[(size_t)z[n]*FD + fo];
}

// ------------------- per-block: atom precompute (gate + concat parts) -------
__global__ __launch_bounds__(256)
void k_gate_pre(const float* __restrict__ Wg,  const float* __restrict__ bg,
                const float* __restrict__ We1b, const float* __restrict__ Wa1b, int N)
{
    __shared__ float sv[8][FD];
    const int warp = threadIdx.x >> 5, lane = threadIdx.x & 31;
    const int fo = lane * 4;
    for (int base = blockIdx.x * 8; base < N; base += gridDim.x * 8){
        int na = N - base; if (na > 8) na = 8;
        __syncthreads();
        for (int idx = threadIdx.x; idx < na * 32; idx += blockDim.x){
            int rr = idx >> 5, cc = (idx & 31) * 4;
            *(float4*)&sv[rr][cc] = *(const float4*)&g_v[(size_t)(base+rr)*FD + cc];
        }
        __syncthreads();
        if (warp < 5){
            const float* W = (warp == 0) ? Wg
                           : (warp == 1) ? We1b
                           : (warp == 2) ? (We1b + FD*FD)
                           : (warp == 3) ? Wa1b
                           :               (Wa1b + FD*FD);
            float4 acc[8];
            #pragma unroll
            for (int j = 0; j < 8; j++) acc[j] = make_float4(0,0,0,0);
            #pragma unroll 4
            for (int k4 = 0; k4 < 32; k4++){
                float4 w0 = *(const float4*)&W[(k4*4+0)*FD + fo];
                float4 w1 = *(const float4*)&W[(k4*4+1)*FD + fo];
                float4 w2 = *(const float4*)&W[(k4*4+2)*FD + fo];
                float4 w3 = *(const float4*)&W[(k4*4+3)*FD + fo];
                #pragma unroll
                for (int j = 0; j < 8; j++){
                    float4 s = *(const float4*)&sv[j][k4*4];
                    fma4(acc[j], s.x, w0); fma4(acc[j], s.y, w1);
                    fma4(acc[j], s.z, w2); fma4(acc[j], s.w, w3);
                }
            }
            if (warp == 0){
                float4 b4 = *(const float4*)&bg[fo];
                for (int j = 0; j < na; j++)
                    *(float4*)&g_gate[(size_t)(base+j)*FD + fo] = sigm4(add4(acc[j], b4));
            } else {
                float* dst = (warp == 1) ? g_pi : (warp == 2) ? g_pj : (warp == 3) ? g_pai : g_paj;
                for (int j = 0; j < na; j++)
                    *(float4*)&dst[(size_t)(base+j)*FD + fo] = acc[j];
            }
        }
    }
}

// ------------------- per-block: angle message scatter -----------------------
// Two angles per warp-iteration: the 16 smem weight loads serve both angles,
// halving the crossbar traffic that bounds this kernel.
__global__ __launch_bounds__(256)
void k_angle(const float* __restrict__ Wang, int A)
{
    __shared__ float sW[16 * FD];
    for (int i = threadIdx.x; i < 16*FD/4; i += blockDim.x)
        ((float4*)sW)[i] = ((const float4*)Wang)[i];
    __syncthreads();
    const int lane = threadIdx.x & 31;
    const int fo = lane * 4;
    int gw = (blockIdx.x * blockDim.x + threadIdx.x) >> 5;
    int nw = (gridDim.x * blockDim.x) >> 5;
    for (int a0 = gw * 2; a0 < A; a0 += nw * 2){
        const int a1 = a0 + 1;
        const bool has2 = (a1 < A);
        int iij0 = g_iij[a0], kat0 = g_kat[a0];
        int iij1 = has2 ? g_iij[a1] : 0;
        int kat1 = has2 ? g_kat[a1] : 0;
        float4 gte0 = *(const float4*)&g_gate[(size_t)kat0*FD + fo];
        float4 gte1 = *(const float4*)&g_gate[(size_t)kat1*FD + fo];
        const float4* af0 = (const float4*)&g_angf[(size_t)a0*16];
        const float4* af1 = (const float4*)&g_angf[(size_t)a1*16];
        float4 acc0 = make_float4(0,0,0,0);
        float4 acc1 = make_float4(0,0,0,0);
        #pragma unroll
        for (int k4 = 0; k4 < 4; k4++){
            float4 w0 = *(const float4*)&sW[(k4*4+0)*FD + fo];
            float4 w1 = *(const float4*)&sW[(k4*4+1)*FD + fo];
            float4 w2 = *(const float4*)&sW[(k4*4+2)*FD + fo];
            float4 w3 = *(const float4*)&sW[(k4*4+3)*FD + fo];
            float4 s0 = af0[k4];
            fma4(acc0, s0.x, w0); fma4(acc0, s0.y, w1);
            fma4(acc0, s0.z, w2); fma4(acc0, s0.w, w3);
            if (has2){
                float4 s1 = af1[k4];
                fma4(acc1, s1.x, w0); fma4(acc1, s1.y, w1);
                fma4(acc1, s1.z, w2); fma4(acc1, s1.w, w3);
            }
        }
        red4(&g_agg[(size_t)iij0*FD + fo], mul4(acc0, gte0));
        if (has2) red4(&g_agg[(size_t)iij1*FD + fo], mul4(acc1, gte1));
    }
}

// ------------------- per-block: fused edge update, bf16 MMA, 8 warps --------
// 256 threads, TILE_E=32, grid <= 148 (1 CTA/SM), software-pipelined tiles.
#define TILE_E 32
#define EDGE_GRID 148
#define SMEM_EDGE_BYTES ((3*64*128 + 32*64 + 32*128 + 2*5*FD + 3*FD) * 4)

// A pair-index swizzle: conflict-free fragment loads
__device__ __forceinline__ int szA(int row){
    return ((row & 7) * 8) ^ (((row >> 2) & 1) * 4);
}

__device__ __forceinline__ void gemm_compute(const uint32_t* __restrict__ sW,
                                             const uint32_t* __restrict__ sA,
                                             int warp, int lane, float c[4][4])
{
    const int rt  = warp >> 2;
    const int cw  = warp & 3;
    const int gid = lane >> 2;
    const int t   = lane & 3;
    const int r0  = rt*16 + gid, r1 = r0 + 8;
    const int sza = szA(r0);
    #pragma unroll
    for (int i = 0; i < 4; i++){ c[i][0]=0.f; c[i][1]=0.f; c[i][2]=0.f; c[i][3]=0.f; }
    #pragma unroll
    for (int kk = 0; kk < 8; kk++){
        const int p0 = kk*8 + t;
        const int p1 = p0 + 4;
        uint32_t a0 = sA[r0*64 + (p0 ^ sza)];
        uint32_t a1 = sA[r1*64 + (p0 ^ sza)];
        uint32_t a2 = sA[r0*64 + (p1 ^ sza)];
        uint32_t a3 = sA[r1*64 + (p1 ^ sza)];
        #pragma unroll
        for (int i = 0; i < 4; i++){
            const int col = (cw*4 + i)*8 + gid;
            uint32_t b0 = sW[p0*128 + (col ^ (t*8))];
            uint32_t b1 = sW[p1*128 + (col ^ (t*8))];
            mma_bf16(c[i], a0, a1, a2, a3, b0, b1);
        }
    }
}

__device__ __forceinline__ void gemm_store(float* __restrict__ sD,
                                           int warp, int lane, const float c[4][4])
{
    const int rt  = warp >> 2;
    const int cw  = warp & 3;
    const int gid = lane >> 2;
    const int t   = lane & 3;
    const int r0  = rt*16 + gid, r1 = r0 + 8;
    const int sz  = (gid & 3) * 8;
    #pragma unroll
    for (int i = 0; i < 4; i++){
        const int colb = (cw*4 + i)*8 + 2*t;
        *(float2*)&sD[r0*128 + (colb ^ sz)] = make_float2(c[i][0], c[i][1]);
        *(float2*)&sD[r1*128 + (colb ^ sz)] = make_float2(c[i][2], c[i][3]);
    }
}

__device__ __forceinline__ void stA_bf16(uint32_t* __restrict__ sA, int row, int lane, float4 v){
    const int p  = lane * 2;
    const int sz = szA(row);
    uint2 u = make_uint2(bf2pack(v.x, v.y), bf2pack(v.z, v.w));
    *(uint2*)&sA[row*64 + (p ^ sz)] = u;
}
__device__ __forceinline__ float4 ldD(const float* __restrict__ sD, int row, int fo){
    return *(const float4*)&sD[row*128 + (fo ^ ((row & 3)*8))];
}

// load one tile's per-edge inputs (indices, ef0, agg, e) into registers
__device__ __forceinline__ void load_tile(const int* __restrict__ edge_index, int E,
                                          int base, int fo,
                                          bool ok[4], int sendi[4], int recvi[4],
                                          float ef[4][5], float4 aggr[4], float4 cur[4])
{
    #pragma unroll
    for (int j = 0; j < 4; j++){
        const int eid = base + j;
        ok[j] = (eid < E);
        if (ok[j]){
            sendi[j] = edge_index[eid];
            recvi[j] = edge_index[E + eid];
            #pragma unroll
            for (int n = 0; n < 5; n++) ef[j][n] = g_ef0[(size_t)eid*5 + n];
            aggr[j] = *(const float4*)&g_agg[(size_t)eid*FD + fo];
            cur[j]  = *(const float4*)&g_e[(size_t)eid*FD + fo];
        } else {
            sendi[j] = 0; recvi[j] = 0;
            #pragma unroll
            for (int n = 0; n < 5; n++) ef[j][n] = 0.0f;
            aggr[j] = make_float4(0,0,0,0);
            cur[j]  = make_float4(0,0,0,0);
        }
    }
}

__global__ __launch_bounds__(256, 1)
void k_edge_fused(const float* __restrict__ Wtb,  const float* __restrict__ btb,
                  const float* __restrict__ We1e, const float* __restrict__ be1,
                  const float* __restrict__ We0,
                  const float* __restrict__ Wa1e, const float* __restrict__ ba1,
                  const float* __restrict__ Wa0,
                  const int* __restrict__ edge_index, int E)
{
    extern __shared__ char smraw[];
    uint32_t* sWtb = (uint32_t*)smraw;
    uint32_t* sWe1 = sWtb + 64*128;
    uint32_t* sWa1 = sWe1 + 64*128;
    uint32_t* sA   = sWa1 + 64*128;
    float*    sD   = (float*)(sA + 32*64);
    float*    sWe0 = sD + 32*128;
    float*    sWa0 = sWe0 + 5*FD;
    float*    sbtb = sWa0 + 5*FD;
    float*    sbe1 = sbtb + FD;
    float*    sba1 = sbe1 + FD;

    for (int i = threadIdx.x; i < FD*FD/2; i += blockDim.x){
        int p = i >> 7, col = i & 127;
        int dst = p*128 + (col ^ ((p & 3)*8));
        sWtb[dst] = bf2pack(Wtb [(2*p)*FD + col], Wtb [(2*p+1)*FD + col]);
        sWe1[dst] = bf2pack(We1e[(2*p)*FD + col], We1e[(2*p+1)*FD + col]);
        sWa1[dst] = bf2pack(Wa1e[(2*p)*FD + col], Wa1e[(2*p+1)*FD + col]);
    }
    for (int i = threadIdx.x; i < 5*FD; i += blockDim.x){
        sWe0[i] = We0[i];
        sWa0[i] = Wa0[i];
    }
    if (threadIdx.x < FD){
        sbtb[threadIdx.x] = btb[threadIdx.x];
        sbe1[threadIdx.x] = be1[threadIdx.x];
        sba1[threadIdx.x] = ba1[threadIdx.x];
    }

    const int warp = threadIdx.x >> 5;
    const int lane = threadIdx.x & 31;
    const int fo = lane * 4;
    const int step = gridDim.x * TILE_E;
    const float4 zero4 = make_float4(0,0,0,0);
    float c[4][4];

    // pipeline state for current tile
    bool  ok[4];
    int   sendi[4], recvi[4];
    float ef[4][5];
    float4 aggr[4], cur[4], pi_pre[4], pj_pre[4];

    int base0 = blockIdx.x * TILE_E;
    if (base0 < E){
        load_tile(edge_index, E, base0 + warp*4, fo, ok, sendi, recvi, ef, aggr, cur);
        #pragma unroll
        for (int j = 0; j < 4; j++){
            pi_pre[j] = *(const float4*)&g_pi[(size_t)sendi[j]*FD + fo];
            pj_pre[j] = *(const float4*)&g_pj[(size_t)recvi[j]*FD + fo];
        }
    }
    __syncthreads();   // weights ready

    for (; base0 < E; base0 += step){
        const int base = base0 + warp * 4;

        #pragma unroll
        for (int j = 0; j < 4; j++) stA_bf16(sA, warp*4 + j, lane, aggr[j]);
        __syncthreads();                                   // s1: A ready

        // ---- stage 1: e1 = e + swish(agg @ Wtb + btb)
        gemm_compute(sWtb, sA, warp, lane, c);
        gemm_store(sD, warp, lane, c);
        __syncthreads();                                   // s2: D ready
        {
            float4 b4 = *(const float4*)&sbtb[fo];
            #pragma unroll
            for (int j = 0; j < 4; j++){
                const int row = warp*4 + j;
                float4 d = ldD(sD, row, fo);
                cur[j] = add4(cur[j], swish4(add4(d, b4)));
                stA_bf16(sA, row, lane, cur[j]);
            }
        }
        __syncthreads();                                   // s3: A ready

        // ---- stage 2: e2 = e1 + swish(pi[s]+pj[r]+e1@We1e+be1) * (ef0@We0)
        gemm_compute(sWe1, sA, warp, lane, c);
        gemm_store(sD, warp, lane, c);
        __syncthreads();                                   // s4: D ready
        float4 pai_pre[4], paj_pre[4];
        {
            float4 p0[4];
            #pragma unroll
            for (int j = 0; j < 4; j++) p0[j] = zero4;
            #pragma unroll
            for (int n = 0; n < 5; n++){
                float4 w = *(const float4*)&sWe0[n*FD + fo];
                #pragma unroll
                for (int j = 0; j < 4; j++) fma4(p0[j], ef[j][n], w);
            }
            float4 b4 = *(const float4*)&sbe1[fo];
            #pragma unroll
            for (int j = 0; j < 4; j++){
                const int row = warp*4 + j;
                float4 d = ldD(sD, row, fo);
                float4 pre = make_float4(d.x+b4.x+pi_pre[j].x+pj_pre[j].x,
                                         d.y+b4.y+pi_pre[j].y+pj_pre[j].y,
                                         d.z+b4.z+pi_pre[j].z+pj_pre[j].z,
                                         d.w+b4.w+pi_pre[j].w+pj_pre[j].w);
                cur[j] = add4(cur[j], mul4(swish4(pre), p0[j]));
                if (ok[j]) *(float4*)&g_e[(size_t)(base+j)*FD + fo] = cur[j];
                stA_bf16(sA, row, lane, cur[j]);
                pai_pre[j] = *(const float4*)&g_pai[(size_t)sendi[j]*FD + fo];
                paj_pre[j] = *(const float4*)&g_paj[(size_t)recvi[j]*FD + fo];
            }
        }
        __syncthreads();                                   // s5: A ready

        // ---- stage 3: v[recv] += swish(pai[s]+paj[r]+e2@Wa1e+ba1) * (ef0@Wa0)
        gemm_compute(sWa1, sA, warp, lane, c);
        gemm_store(sD, warp, lane, c);

        // prefetch NEXT tile while this sync + epilogue run
        const int nbase0 = base0 + step;
        const bool have_next = (nbase0 < E);
        bool  nok[4];
        int   nsend[4], nrecv[4];
        float nef[4][5];
        float4 nagg[4], ncur[4];
        if (have_next)
            load_tile(edge_index, E, nbase0 + warp*4, fo, nok, nsend, nrecv, nef, nagg, ncur);

        __syncthreads();                                   // s6: D ready
        {
            float4 p0[4];
            #pragma unroll
            for (int j = 0; j < 4; j++) p0[j] = zero4;
            #pragma unroll
            for (int n = 0; n < 5; n++){
                float4 w = *(const float4*)&sWa0[n*FD + fo];
                #pragma unroll
                for (int j = 0; j < 4; j++) fma4(p0[j], ef[j][n], w);
            }
            float4 b4 = *(const float4*)&sba1[fo];
            #pragma unroll
            for (int j = 0; j < 4; j++){
                if (ok[j]){
                    const int row = warp*4 + j;
                    float4 d = ldD(sD, row, fo);
                    float4 pre = make_float4(d.x+b4.x+pai_pre[j].x+paj_pre[j].x,
                                             d.y+b4.y+pai_pre[j].y+paj_pre[j].y,
                                             d.z+b4.z+pai_pre[j].z+paj_pre[j].z,
                                             d.w+b4.w+pai_pre[j].w+paj_pre[j].w);
                    float4 m = mul4(swish4(pre), p0[j]);
                    red4(&g_v[(size_t)recvi[j]*FD + fo], m);
                }
            }
        }
        // commit next tile into pipeline state + start pi/pj gathers
        if (have_next){
            #pragma unroll
            for (int j = 0; j < 4; j++){
                ok[j] = nok[j]; sendi[j] = nsend[j]; recvi[j] = nrecv[j];
                #pragma unroll
                for (int n = 0; n < 5; n++) ef[j][n] = nef[j][n];
                aggr[j] = nagg[j]; cur[j] = ncur[j];
                pi_pre[j] = *(const float4*)&g_pi[(size_t)sendi[j]*FD + fo];
                pj_pre[j] = *(const float4*)&g_pj[(size_t)recvi[j]*FD + fo];
            }
        }
        // no end barrier needed: s1 separates this tile's sD reads from the
        // next tile's gemm_store, and s6 already separated sA reads from stA.
    }
}

// ------------------- final readout MLP -------------------------------------
__global__ __launch_bounds__(128)
void k_final(const float* __restrict__ W1, const float* __restrict__ b1,
             const float* __restrict__ W2, const float* __restrict__ b2,
             const float* __restrict__ W3, const float* __restrict__ b3,
             float* __restrict__ out, int N)
{
    __shared__ float sv[FD];
    __shared__ float sh[FD];
    __shared__ float sred[4];
    int n = blockIdx.x;
    if (n >= N) return;
    int t = threadIdx.x;
    sv[t] = g_v[(size_t)n*FD + t];
    __syncthreads();
    float acc = b1[t];
    #pragma unroll 8
    for (int k = 0; k < FD; k++) acc = fmaf(sv[k], W1[k*FD + t], acc);
    sh[t] = swishf(acc);
    __syncthreads();
    acc = b2[t];
    #pragma unroll 8
    for (int k = 0; k < FD; k++) acc = fmaf(sh[k], W2[k*FD + t], acc);
    float prod = swishf(acc) * W3[t];
    #pragma unroll
    for (int o = 16; o > 0; o >>= 1) prod += __shfl_down_sync(0xffffffffu, prod, o);
    if ((t & 31) == 0) sred[t >> 5] = prod;
    __syncthreads();
    if (t == 0) out[n] = sred[0] + sred[1] + sred[2] + sred[3] + b3[0];
}

// ------------------------- launch ------------------------------------------
extern "C" void kernel_launch(void* const* d_in, const int* in_sizes, int n_in,
                              void* d_out, int out_size)
{
    const int*   atomic_numbers = (const int*  )d_in[0];
    const int*   edge_index     = (const int*  )d_in[1];
    const float* edge_dist      = (const float*)d_in[2];
    const int*   tbi            = (const int*  )d_in[3];
    const float* norm_ik        = (const float*)d_in[4];
    const float* cos_ang        = (const float*)d_in[5];
    const int*   tnb            = (const int*  )d_in[6];
    const int*   tna            = (const int*  )d_in[7];
    const float* emb            = (const float*)d_in[8];
    const float* W_enc          = (const float*)d_in[9];
    const float* b_enc          = (const float*)d_in[10];
    const float* W_angle        = (const float*)d_in[11];
    const float* Wg             = (const float*)d_in[12];
    const float* bg             = (const float*)d_in[13];
    const float* W_tb           = (const float*)d_in[14];
    const float* b_tb           = (const float*)d_in[15];
    const float* We1            = (const float*)d_in[16];
    const float* be1            = (const float*)d_in[17];
    const float* We0            = (const float*)d_in[18];
    const float* Wa1            = (const float*)d_in[19];
    const float* ba1            = (const float*)d_in[20];
    const float* Wa0            = (const float*)d_in[21];
    const float* W1             = (const float*)d_in[22];
    const float* b1             = (const float*)d_in[23];
    const float* W2             = (const float*)d_in[24];
    const float* b2             = (const float*)d_in[25];
    const float* W3             = (const float*)d_in[26];
    const float* b3             = (const float*)d_in[27];

    const int N = in_sizes[0];
    const int E = in_sizes[2];
    const int A = in_sizes[4];
    const int G = in_sizes[6];
    float* out = (float*)d_out;

    cudaFuncSetAttribute(k_edge_fused, cudaFuncAttributeMaxDynamicSharedMemorySize,
                         SMEM_EDGE_BYTES);

    float* aggp = nullptr;
    cudaGetSymbolAddress((void**)&aggp, g_agg);

    k_offsets  <<<1, 32>>>(tnb, tna, G);
    k_angle_pre<<<(A + 255) / 256, 256>>>(tbi, norm_ik, cos_ang, edge_index, A, E, G);
    k_edge_init<<<(E + 3) / 4, 128>>>(edge_dist, W_enc, b_enc, E);
    k_vinit    <<<(N * 32 + 255) / 256, 256>>>(atomic_numbers, emb, N);

    for (int b = 0; b < 4; b++){
        cudaMemsetAsync(aggp, 0, (size_t)E * FD * sizeof(float), 0);
        k_gate_pre<<<(N + 7) / 8, 256>>>(Wg + (size_t)b*FD*FD, bg + (size_t)b*FD,
                                         We1 + (size_t)b*3*FD*FD, Wa1 + (size_t)b*3*FD*FD, N);
        k_angle<<<1184, 256>>>(W_angle + (size_t)b*16*FD, A);
        k_edge_fused<<<EDGE_GRID, 256, SMEM_EDGE_BYTES>>>(
            W_tb + (size_t)b*FD*FD,            b_tb + (size_t)b*FD,
            We1  + (size_t)b*3*FD*FD + 2*FD*FD, be1 + (size_t)b*FD,
            We0  + (size_t)b*5*FD,
            Wa1  + (size_t)b*3*FD*FD + 2*FD*FD, ba1 + (size_t)b*FD,
            Wa0  + (size_t)b*5*FD,
            edge_index, E);
    }

    k_final<<<N, 128>>>(W1, b1, W2, b2, W3, b3, out, N);
}